// round 2
// baseline (speedup 1.0000x reference)
#include <cuda_runtime.h>

// Problem constants
#define EDIM   1024
#define NH     16
#define HD     64
#define SEQ    2048
#define NB     2
#define NTOK   (NB * SEQ)      // 4096 tokens
#define E3     (3 * EDIM)      // 3072
#define LR     128             // LoRA rank
#define LSCALE (1.0f / 128.0f) // lora scaling

// Scratch (no cudaMalloc allowed -> __device__ globals)
__device__ float g_aeff[LR * EDIM];              // 0.5 MB  A_eff = sum of 3 col blocks of A_in
__device__ float g_wtot[E3 * EDIM];              // 12.6 MB W_total = W_eff + s * B_in @ A_eff
__device__ float g_qkv[(size_t)NTOK * E3];       // 50 MB   qkv = x @ W_total^T
__device__ float g_attn[(size_t)NTOK * EDIM];    // 16.8 MB attention output (token-major)

// ---------------------------------------------------------------------------
// Kernel 1: A_eff[r,e] = A_in[r,e] + A_in[r,E+e] + A_in[r,2E+e]
// ---------------------------------------------------------------------------
__global__ void aeff_kernel(const float* __restrict__ A_in) {
    int i = blockIdx.x * blockDim.x + threadIdx.x;
    if (i >= LR * EDIM) return;
    int r = i >> 10;          // /1024
    int e = i & (EDIM - 1);
    const float* row = A_in + (size_t)r * E3;
    g_aeff[i] = row[e] + row[e + EDIM] + row[e + 2 * EDIM];
}

// ---------------------------------------------------------------------------
// Kernel 2: W_total[j,e] = sum_c W_in[j, c*E+e] + s * sum_r B_in[j,r]*A_eff[r,e]
// block = 256 threads = 32(e) x 8(j); grid = (E/32, 3E/8)
// ---------------------------------------------------------------------------
__global__ __launch_bounds__(256) void wtotal_kernel(const float* __restrict__ W_in,
                                                     const float* __restrict__ B_in) {
    __shared__ float As[LR][32];  // A_eff tile [r][e] 16 KB
    __shared__ float Bs[8][LR];   // B_in rows   4 KB
    const int e0 = blockIdx.x * 32;
    const int j0 = blockIdx.y * 8;
    const int tid = threadIdx.x;

    #pragma unroll
    for (int i = tid; i < LR * 32; i += 256) {
        int r = i >> 5, e = i & 31;
        As[r][e] = g_aeff[r * EDIM + e0 + e];
    }
    #pragma unroll
    for (int i = tid; i < 8 * LR; i += 256) {
        int j = i >> 7, r = i & 127;
        Bs[j][r] = B_in[(size_t)(j0 + j) * LR + r];
    }
    __syncthreads();

    const int tx = tid & 31;   // e
    const int ty = tid >> 5;   // j (== warp id -> Bs broadcast)
    float acc = 0.f;
    #pragma unroll 8
    for (int r = 0; r < LR; r++)
        acc += Bs[ty][r] * As[r][tx];

    const int j = j0 + ty;
    const int e = e0 + tx;
    const float* wrow = W_in + (size_t)j * E3;
    g_wtot[(size_t)j * EDIM + e] =
        wrow[e] + wrow[e + EDIM] + wrow[e + 2 * EDIM] + LSCALE * acc;
}

// ---------------------------------------------------------------------------
// Generic NT SGEMM: C[M,N] = A[M,K] . B[N,K]^T  (both row-major, dot along K)
// 128x128 tile, BK=16, 256 threads, 8x8 register micro-tile.
// ---------------------------------------------------------------------------
template <int M, int N, int K>
__device__ __forceinline__ void sgemm_nt_body(const float* __restrict__ A,
                                              const float* __restrict__ B,
                                              float* __restrict__ C) {
    constexpr int BM = 128, BN = 128, BK = 16;
    __shared__ float As[BK][BM + 4];  // +4 keeps float4 alignment, cuts store conflicts
    __shared__ float Bs[BK][BN + 4];

    const int tid = threadIdx.x;
    const int tn = tid & 15;   // 16 threads along N
    const int tm = tid >> 4;   // 16 threads along M
    const int m0 = blockIdx.y * BM;
    const int n0 = blockIdx.x * BN;

    float acc[8][8];
    #pragma unroll
    for (int i = 0; i < 8; i++)
        #pragma unroll
        for (int j = 0; j < 8; j++) acc[i][j] = 0.f;

    for (int k0 = 0; k0 < K; k0 += BK) {
        #pragma unroll
        for (int i = 0; i < (BM * BK) / 256; i++) {   // 8 loads/thread
            int idx = tid + i * 256;
            int row = idx >> 4, kk = idx & 15;
            As[kk][row] = A[(size_t)(m0 + row) * K + k0 + kk];
        }
        #pragma unroll
        for (int i = 0; i < (BN * BK) / 256; i++) {
            int idx = tid + i * 256;
            int row = idx >> 4, kk = idx & 15;
            Bs[kk][row] = B[(size_t)(n0 + row) * K + k0 + kk];
        }
        __syncthreads();

        #pragma unroll
        for (int kk = 0; kk < BK; kk++) {
            float a[8], b[8];
            float4 t0 = *(const float4*)&As[kk][tm * 8];
            float4 t1 = *(const float4*)&As[kk][tm * 8 + 4];
            float4 u0 = *(const float4*)&Bs[kk][tn * 8];
            float4 u1 = *(const float4*)&Bs[kk][tn * 8 + 4];
            a[0] = t0.x; a[1] = t0.y; a[2] = t0.z; a[3] = t0.w;
            a[4] = t1.x; a[5] = t1.y; a[6] = t1.z; a[7] = t1.w;
            b[0] = u0.x; b[1] = u0.y; b[2] = u0.z; b[3] = u0.w;
            b[4] = u1.x; b[5] = u1.y; b[6] = u1.z; b[7] = u1.w;
            #pragma unroll
            for (int i = 0; i < 8; i++)
                #pragma unroll
                for (int j = 0; j < 8; j++)
                    acc[i][j] += a[i] * b[j];
        }
        __syncthreads();
    }

    #pragma unroll
    for (int i = 0; i < 8; i++) {
        int m = m0 + tm * 8 + i;
        float4 v0 = make_float4(acc[i][0], acc[i][1], acc[i][2], acc[i][3]);
        float4 v1 = make_float4(acc[i][4], acc[i][5], acc[i][6], acc[i][7]);
        *(float4*)&C[(size_t)m * N + n0 + tn * 8] = v0;
        *(float4*)&C[(size_t)m * N + n0 + tn * 8 + 4] = v1;
    }
}

__global__ __launch_bounds__(256, 2) void sgemm_qkv_kernel(const float* __restrict__ x) {
    sgemm_nt_body<NTOK, E3, EDIM>(x, g_wtot, g_qkv);
}
__global__ __launch_bounds__(256, 2) void sgemm_out_kernel(const float* __restrict__ Wout,
                                                           float* __restrict__ out) {
    sgemm_nt_body<NTOK, EDIM, EDIM>(g_attn, Wout, out);
}

// ---------------------------------------------------------------------------
// Flash attention, fp32. One thread = one query row. Block = 128 queries.
// Grid = (SEQ/128, NH, NB). K/V tiles of 32 keys staged in smem (broadcast reads).
// ---------------------------------------------------------------------------
#define QT 128
#define KT 32

__global__ __launch_bounds__(128) void attention_kernel() {
    __shared__ float Ks[KT][HD];
    __shared__ float Vs[KT][HD];

    const int t  = threadIdx.x;
    const int q0 = blockIdx.x * QT;
    const int h  = blockIdx.y;
    const int b  = blockIdx.z;
    const int tok = b * SEQ + q0 + t;

    // q (pre-scaled by 1/sqrt(D)) and o accumulator live in registers
    float q[HD], o[HD];
    const float* qptr = g_qkv + (size_t)tok * E3 + h * HD;
    #pragma unroll
    for (int d4 = 0; d4 < HD / 4; d4++) {
        float4 v = *(const float4*)(qptr + 4 * d4);
        q[4 * d4 + 0] = v.x * 0.125f;
        q[4 * d4 + 1] = v.y * 0.125f;
        q[4 * d4 + 2] = v.z * 0.125f;
        q[4 * d4 + 3] = v.w * 0.125f;
    }
    #pragma unroll
    for (int d = 0; d < HD; d++) o[d] = 0.f;

    float m = -1e30f, l = 0.f;

    const float* kbase = g_qkv + (size_t)b * SEQ * E3 + EDIM + h * HD;      // K block
    const float* vbase = g_qkv + (size_t)b * SEQ * E3 + 2 * EDIM + h * HD;  // V block

    for (int k0 = 0; k0 < SEQ; k0 += KT) {
        // stage K,V tiles: 512 float4 each half -> 4 float4 per thread
        #pragma unroll
        for (int i = 0; i < (KT * HD) / (128 * 4); i++) {
            int idx = t + i * 128;        // float4 slot
            int kk = idx >> 4, d4 = idx & 15;
            size_t off = (size_t)(k0 + kk) * E3 + d4 * 4;
            *(float4*)&Ks[kk][d4 * 4] = *(const float4*)(kbase + off);
            *(float4*)&Vs[kk][d4 * 4] = *(const float4*)(vbase + off);
        }
        __syncthreads();

        float s[KT];
        #pragma unroll
        for (int kk = 0; kk < KT; kk++) {
            float s0 = 0.f, s1 = 0.f, s2 = 0.f, s3 = 0.f;
            #pragma unroll
            for (int d4 = 0; d4 < HD / 4; d4++) {
                float4 kv = *(const float4*)&Ks[kk][4 * d4];
                s0 += q[4 * d4 + 0] * kv.x;
                s1 += q[4 * d4 + 1] * kv.y;
                s2 += q[4 * d4 + 2] * kv.z;
                s3 += q[4 * d4 + 3] * kv.w;
            }
            s[kk] = (s0 + s1) + (s2 + s3);
        }

        float tmax = s[0];
        #pragma unroll
        for (int kk = 1; kk < KT; kk++) tmax = fmaxf(tmax, s[kk]);
        float mnew = fmaxf(m, tmax);
        float corr = __expf(m - mnew);
        l *= corr;
        #pragma unroll
        for (int d = 0; d < HD; d++) o[d] *= corr;

        #pragma unroll
        for (int kk = 0; kk < KT; kk++) {
            float p = __expf(s[kk] - mnew);
            l += p;
            #pragma unroll
            for (int d4 = 0; d4 < HD / 4; d4++) {
                float4 vv = *(const float4*)&Vs[kk][4 * d4];
                o[4 * d4 + 0] += p * vv.x;
                o[4 * d4 + 1] += p * vv.y;
                o[4 * d4 + 2] += p * vv.z;
                o[4 * d4 + 3] += p * vv.w;
            }
        }
        m = mnew;
        __syncthreads();
    }

    const float inv = 1.f / l;
    float* optr = g_attn + (size_t)tok * EDIM + h * HD;
    #pragma unroll
    for (int d4 = 0; d4 < HD / 4; d4++) {
        float4 v = make_float4(o[4 * d4 + 0] * inv, o[4 * d4 + 1] * inv,
                               o[4 * d4 + 2] * inv, o[4 * d4 + 3] * inv);
        *(float4*)(optr + 4 * d4) = v;
    }
}

// ---------------------------------------------------------------------------
// Launch: inputs are (x, W_in, A_in, B_in, W_out); output fp32 [2,2048,1024]
// ---------------------------------------------------------------------------
extern "C" void kernel_launch(void* const* d_in, const int* in_sizes, int n_in,
                              void* d_out, int out_size) {
    const float* x     = (const float*)d_in[0];
    const float* W_in  = (const float*)d_in[1];
    const float* A_in  = (const float*)d_in[2];
    const float* B_in  = (const float*)d_in[3];
    const float* W_out = (const float*)d_in[4];
    float* out = (float*)d_out;

    aeff_kernel<<<(LR * EDIM + 255) / 256, 256>>>(A_in);
    wtotal_kernel<<<dim3(EDIM / 32, E3 / 8), 256>>>(W_in, B_in);
    sgemm_qkv_kernel<<<dim3(E3 / 128, NTOK / 128), 256>>>(x);
    attention_kernel<<<dim3(SEQ / QT, NH, NB), 128>>>();
    sgemm_out_kernel<<<dim3(EDIM / 128, NTOK / 128), 256>>>(W_out, out);
}

// round 3
// speedup vs baseline: 2.2846x; 2.2846x over previous
#include <cuda_runtime.h>
#include <cstdint>

// Problem constants
#define EDIM   1024
#define NH     16
#define HD     64
#define SEQ    2048
#define NB     2
#define NTOK   (NB * SEQ)      // 4096 tokens
#define E3     (3 * EDIM)      // 3072
#define LR     128             // LoRA rank
#define LSCALE (1.0f / 128.0f) // lora scaling

// Scratch (no cudaMalloc allowed -> __device__ globals)
__device__ float g_aeff[LR * EDIM];              // A_eff = sum of 3 col blocks of A_in
__device__ float g_wtot[E3 * EDIM];              // W_total = W_eff + s * B_in @ A_eff
__device__ float g_qkv[(size_t)NTOK * E3];       // qkv = x @ W_total^T
__device__ float g_attn[(size_t)NTOK * EDIM];    // attention output (token-major)

// ---------------------------------------------------------------------------
// tf32 helpers
// ---------------------------------------------------------------------------
__device__ __forceinline__ uint32_t f2tf(float f) {
    uint32_t u;
    asm("cvt.rna.tf32.f32 %0, %1;" : "=r"(u) : "f"(f));
    return u;
}

__device__ __forceinline__ void mma_tf32(float* d, const uint32_t* a, const uint32_t* b) {
    asm volatile(
        "mma.sync.aligned.m16n8k8.row.col.f32.tf32.tf32.f32 "
        "{%0,%1,%2,%3}, {%4,%5,%6,%7}, {%8,%9}, {%0,%1,%2,%3};\n"
        : "+f"(d[0]), "+f"(d[1]), "+f"(d[2]), "+f"(d[3])
        : "r"(a[0]), "r"(a[1]), "r"(a[2]), "r"(a[3]), "r"(b[0]), "r"(b[1]));
}

// ---------------------------------------------------------------------------
// Kernel 1: A_eff[r,e] = A_in[r,e] + A_in[r,E+e] + A_in[r,2E+e]
// ---------------------------------------------------------------------------
__global__ void aeff_kernel(const float* __restrict__ A_in) {
    int i = blockIdx.x * blockDim.x + threadIdx.x;
    if (i >= LR * EDIM) return;
    int r = i >> 10;
    int e = i & (EDIM - 1);
    const float* row = A_in + (size_t)r * E3;
    g_aeff[i] = row[e] + row[e + EDIM] + row[e + 2 * EDIM];
}

// ---------------------------------------------------------------------------
// Kernel 2: W_total[j,e] = sum_c W_in[j, c*E+e] + s * sum_r B_in[j,r]*A_eff[r,e]
// ---------------------------------------------------------------------------
__global__ __launch_bounds__(256) void wtotal_kernel(const float* __restrict__ W_in,
                                                     const float* __restrict__ B_in) {
    __shared__ float As[LR][32];
    __shared__ float Bs[8][LR];
    const int e0 = blockIdx.x * 32;
    const int j0 = blockIdx.y * 8;
    const int tid = threadIdx.x;

    #pragma unroll
    for (int i = tid; i < LR * 32; i += 256) {
        int r = i >> 5, e = i & 31;
        As[r][e] = g_aeff[r * EDIM + e0 + e];
    }
    #pragma unroll
    for (int i = tid; i < 8 * LR; i += 256) {
        int j = i >> 7, r = i & 127;
        Bs[j][r] = B_in[(size_t)(j0 + j) * LR + r];
    }
    __syncthreads();

    const int tx = tid & 31;
    const int ty = tid >> 5;
    float acc = 0.f;
    #pragma unroll 8
    for (int r = 0; r < LR; r++)
        acc += Bs[ty][r] * As[r][tx];

    const int j = j0 + ty;
    const int e = e0 + tx;
    const float* wrow = W_in + (size_t)j * E3;
    g_wtot[(size_t)j * EDIM + e] =
        wrow[e] + wrow[e + EDIM] + wrow[e + 2 * EDIM] + LSCALE * acc;
}

// ---------------------------------------------------------------------------
// tf32 tensor-core NT GEMM: C[M,N] = A[M,K] . B[N,K]^T (both row-major).
// Block 128x128, BK=16, 256 threads (8 warps, 2x4 warp grid -> 64x32 warp tile).
// Register-prefetch pipelining; tf32 rounding (cvt.rna) applied at smem staging.
// smem stride 20 makes every fragment LDS bank-conflict-free.
// ---------------------------------------------------------------------------
template <int M, int N, int K>
__device__ __forceinline__ void mma_nt_body(const float* __restrict__ A,
                                            const float* __restrict__ B,
                                            float* __restrict__ C) {
    constexpr int BM = 128, BN = 128, BK = 16;
    constexpr int LD = BK + 4;  // 20 floats: bank = 20*(lane/4)+lane%4 hits all 32 banks
    __shared__ uint32_t As[BM * LD];
    __shared__ uint32_t Bs[BN * LD];

    const int tid  = threadIdx.x;
    const int lane = tid & 31;
    const int warp = tid >> 5;
    const int wm   = warp & 1;   // 2 warps along M
    const int wn   = warp >> 1;  // 4 warps along N
    const int m0   = blockIdx.y * BM;
    const int n0   = blockIdx.x * BN;

    // staging: thread covers rows (tid/4, tid/4+64), cols [(tid%4)*4 .. +3]
    const int srow = tid >> 2;
    const int skc  = (tid & 3) * 4;

    const float* Ab = A + (size_t)(m0 + srow) * K + skc;
    const float* Bb = B + (size_t)(n0 + srow) * K + skc;
    const size_t rstep = (size_t)64 * K;

    float4 ra0 = *(const float4*)(Ab);
    float4 ra1 = *(const float4*)(Ab + rstep);
    float4 rb0 = *(const float4*)(Bb);
    float4 rb1 = *(const float4*)(Bb + rstep);

    float acc[4][4][4];
    #pragma unroll
    for (int i = 0; i < 4; i++)
        #pragma unroll
        for (int j = 0; j < 4; j++)
            #pragma unroll
            for (int k = 0; k < 4; k++) acc[i][j][k] = 0.f;

    const int quad = lane >> 2;  // groupID (row within fragment)
    const int tq   = lane & 3;   // thread-in-group (k / paired cols)

    constexpr int T = K / BK;
    for (int t = 0; t < T; t++) {
        __syncthreads();  // previous compute done; smem reusable
        {
            uint32_t* p0 = &As[srow * LD + skc];
            p0[0] = f2tf(ra0.x); p0[1] = f2tf(ra0.y); p0[2] = f2tf(ra0.z); p0[3] = f2tf(ra0.w);
            uint32_t* p1 = &As[(srow + 64) * LD + skc];
            p1[0] = f2tf(ra1.x); p1[1] = f2tf(ra1.y); p1[2] = f2tf(ra1.z); p1[3] = f2tf(ra1.w);
            uint32_t* q0 = &Bs[srow * LD + skc];
            q0[0] = f2tf(rb0.x); q0[1] = f2tf(rb0.y); q0[2] = f2tf(rb0.z); q0[3] = f2tf(rb0.w);
            uint32_t* q1 = &Bs[(srow + 64) * LD + skc];
            q1[0] = f2tf(rb1.x); q1[1] = f2tf(rb1.y); q1[2] = f2tf(rb1.z); q1[3] = f2tf(rb1.w);
        }
        __syncthreads();

        if (t + 1 < T) {  // prefetch next tile into registers (hidden by compute)
            const float* An = Ab + (t + 1) * BK;
            const float* Bn = Bb + (t + 1) * BK;
            ra0 = *(const float4*)(An);
            ra1 = *(const float4*)(An + rstep);
            rb0 = *(const float4*)(Bn);
            rb1 = *(const float4*)(Bn + rstep);
        }

        #pragma unroll
        for (int ks = 0; ks < 2; ks++) {
            const int kb = ks * 8;
            uint32_t af[4][4], bf[4][2];
            #pragma unroll
            for (int mi = 0; mi < 4; mi++) {
                const uint32_t* p = &As[(wm * 64 + mi * 16 + quad) * LD + kb + tq];
                af[mi][0] = p[0];           // (row,      k)
                af[mi][1] = p[8 * LD];      // (row+8,    k)
                af[mi][2] = p[4];           // (row,      k+4)
                af[mi][3] = p[8 * LD + 4];  // (row+8,    k+4)
            }
            #pragma unroll
            for (int ni = 0; ni < 4; ni++) {
                const uint32_t* p = &Bs[(wn * 32 + ni * 8 + quad) * LD + kb + tq];
                bf[ni][0] = p[0];  // (k,   n)
                bf[ni][1] = p[4];  // (k+4, n)
            }
            #pragma unroll
            for (int mi = 0; mi < 4; mi++)
                #pragma unroll
                for (int ni = 0; ni < 4; ni++)
                    mma_tf32(acc[mi][ni], af[mi], bf[ni]);
        }
    }

    // epilogue: c0,c1 -> (row, 2*tq..+1); c2,c3 -> (row+8, same cols)
    #pragma unroll
    for (int mi = 0; mi < 4; mi++) {
        const int r = m0 + wm * 64 + mi * 16 + quad;
        #pragma unroll
        for (int ni = 0; ni < 4; ni++) {
            const int c = n0 + wn * 32 + ni * 8 + tq * 2;
            *(float2*)&C[(size_t)r * N + c]       = make_float2(acc[mi][ni][0], acc[mi][ni][1]);
            *(float2*)&C[(size_t)(r + 8) * N + c] = make_float2(acc[mi][ni][2], acc[mi][ni][3]);
        }
    }
}

__global__ __launch_bounds__(256, 2) void mma_qkv_kernel(const float* __restrict__ x) {
    mma_nt_body<NTOK, E3, EDIM>(x, g_wtot, g_qkv);
}
__global__ __launch_bounds__(256, 2) void mma_out_kernel(const float* __restrict__ Wout,
                                                         float* __restrict__ out) {
    mma_nt_body<NTOK, EDIM, EDIM>(g_attn, Wout, out);
}

// ---------------------------------------------------------------------------
// Flash attention, fp32 (unchanged this round; mma port next).
// ---------------------------------------------------------------------------
#define QT 128
#define KT 32

__global__ __launch_bounds__(128) void attention_kernel() {
    __shared__ float Ks[KT][HD];
    __shared__ float Vs[KT][HD];

    const int t  = threadIdx.x;
    const int q0 = blockIdx.x * QT;
    const int h  = blockIdx.y;
    const int b  = blockIdx.z;
    const int tok = b * SEQ + q0 + t;

    float q[HD], o[HD];
    const float* qptr = g_qkv + (size_t)tok * E3 + h * HD;
    #pragma unroll
    for (int d4 = 0; d4 < HD / 4; d4++) {
        float4 v = *(const float4*)(qptr + 4 * d4);
        q[4 * d4 + 0] = v.x * 0.125f;
        q[4 * d4 + 1] = v.y * 0.125f;
        q[4 * d4 + 2] = v.z * 0.125f;
        q[4 * d4 + 3] = v.w * 0.125f;
    }
    #pragma unroll
    for (int d = 0; d < HD; d++) o[d] = 0.f;

    float m = -1e30f, l = 0.f;

    const float* kbase = g_qkv + (size_t)b * SEQ * E3 + EDIM + h * HD;
    const float* vbase = g_qkv + (size_t)b * SEQ * E3 + 2 * EDIM + h * HD;

    for (int k0 = 0; k0 < SEQ; k0 += KT) {
        #pragma unroll
        for (int i = 0; i < (KT * HD) / (128 * 4); i++) {
            int idx = t + i * 128;
            int kk = idx >> 4, d4 = idx & 15;
            size_t off = (size_t)(k0 + kk) * E3 + d4 * 4;
            *(float4*)&Ks[kk][d4 * 4] = *(const float4*)(kbase + off);
            *(float4*)&Vs[kk][d4 * 4] = *(const float4*)(vbase + off);
        }
        __syncthreads();

        float s[KT];
        #pragma unroll
        for (int kk = 0; kk < KT; kk++) {
            float s0 = 0.f, s1 = 0.f, s2 = 0.f, s3 = 0.f;
            #pragma unroll
            for (int d4 = 0; d4 < HD / 4; d4++) {
                float4 kv = *(const float4*)&Ks[kk][4 * d4];
                s0 += q[4 * d4 + 0] * kv.x;
                s1 += q[4 * d4 + 1] * kv.y;
                s2 += q[4 * d4 + 2] * kv.z;
                s3 += q[4 * d4 + 3] * kv.w;
            }
            s[kk] = (s0 + s1) + (s2 + s3);
        }

        float tmax = s[0];
        #pragma unroll
        for (int kk = 1; kk < KT; kk++) tmax = fmaxf(tmax, s[kk]);
        float mnew = fmaxf(m, tmax);
        float corr = __expf(m - mnew);
        l *= corr;
        #pragma unroll
        for (int d = 0; d < HD; d++) o[d] *= corr;

        #pragma unroll
        for (int kk = 0; kk < KT; kk++) {
            float p = __expf(s[kk] - mnew);
            l += p;
            #pragma unroll
            for (int d4 = 0; d4 < HD / 4; d4++) {
                float4 vv = *(const float4*)&Vs[kk][4 * d4];
                o[4 * d4 + 0] += p * vv.x;
                o[4 * d4 + 1] += p * vv.y;
                o[4 * d4 + 2] += p * vv.z;
                o[4 * d4 + 3] += p * vv.w;
            }
        }
        m = mnew;
        __syncthreads();
    }

    const float inv = 1.f / l;
    float* optr = g_attn + (size_t)tok * EDIM + h * HD;
    #pragma unroll
    for (int d4 = 0; d4 < HD / 4; d4++) {
        float4 v = make_float4(o[4 * d4 + 0] * inv, o[4 * d4 + 1] * inv,
                               o[4 * d4 + 2] * inv, o[4 * d4 + 3] * inv);
        *(float4*)(optr + 4 * d4) = v;
    }
}

// ---------------------------------------------------------------------------
// Launch
// ---------------------------------------------------------------------------
extern "C" void kernel_launch(void* const* d_in, const int* in_sizes, int n_in,
                              void* d_out, int out_size) {
    const float* x     = (const float*)d_in[0];
    const float* W_in  = (const float*)d_in[1];
    const float* A_in  = (const float*)d_in[2];
    const float* B_in  = (const float*)d_in[3];
    const float* W_out = (const float*)d_in[4];
    float* out = (float*)d_out;

    aeff_kernel<<<(LR * EDIM + 255) / 256, 256>>>(A_in);
    wtotal_kernel<<<dim3(EDIM / 32, E3 / 8), 256>>>(W_in, B_in);
    mma_qkv_kernel<<<dim3(E3 / 128, NTOK / 128), 256>>>(x);
    attention_kernel<<<dim3(SEQ / QT, NH, NB), 128>>>();
    mma_out_kernel<<<dim3(EDIM / 128, NTOK / 128), 256>>>(W_out, out);
}

// round 4
// speedup vs baseline: 4.1998x; 1.8383x over previous
#include <cuda_runtime.h>
#include <cstdint>

// Problem constants
#define EDIM   1024
#define NH     16
#define HD     64
#define SEQ    2048
#define NB     2
#define NTOK   (NB * SEQ)      // 4096 tokens
#define E3     (3 * EDIM)      // 3072
#define LR     128             // LoRA rank
#define LSCALE (1.0f / 128.0f) // lora scaling

// Scratch (no cudaMalloc allowed -> __device__ globals)
__device__ float g_aeff[LR * EDIM];
__device__ float g_wtot[E3 * EDIM];
__device__ float g_qkv[(size_t)NTOK * E3];
__device__ float g_attn[(size_t)NTOK * EDIM];

// ---------------------------------------------------------------------------
// tf32 helpers
// ---------------------------------------------------------------------------
__device__ __forceinline__ uint32_t f2tf(float f) {
    uint32_t u;
    asm("cvt.rna.tf32.f32 %0, %1;" : "=r"(u) : "f"(f));
    return u;
}

__device__ __forceinline__ void mma_tf32(float* d, const uint32_t* a, const uint32_t* b) {
    asm volatile(
        "mma.sync.aligned.m16n8k8.row.col.f32.tf32.tf32.f32 "
        "{%0,%1,%2,%3}, {%4,%5,%6,%7}, {%8,%9}, {%0,%1,%2,%3};\n"
        : "+f"(d[0]), "+f"(d[1]), "+f"(d[2]), "+f"(d[3])
        : "r"(a[0]), "r"(a[1]), "r"(a[2]), "r"(a[3]), "r"(b[0]), "r"(b[1]));
}

// ---------------------------------------------------------------------------
// Kernel 1: A_eff[r,e] = A_in[r,e] + A_in[r,E+e] + A_in[r,2E+e]
// ---------------------------------------------------------------------------
__global__ void aeff_kernel(const float* __restrict__ A_in) {
    int i = blockIdx.x * blockDim.x + threadIdx.x;
    if (i >= LR * EDIM) return;
    int r = i >> 10;
    int e = i & (EDIM - 1);
    const float* row = A_in + (size_t)r * E3;
    g_aeff[i] = row[e] + row[e + EDIM] + row[e + 2 * EDIM];
}

// ---------------------------------------------------------------------------
// Kernel 2: W_total[j,e] = W_eff + s * B_in @ A_eff
// ---------------------------------------------------------------------------
__global__ __launch_bounds__(256) void wtotal_kernel(const float* __restrict__ W_in,
                                                     const float* __restrict__ B_in) {
    __shared__ float As[LR][32];
    __shared__ float Bs[8][LR];
    const int e0 = blockIdx.x * 32;
    const int j0 = blockIdx.y * 8;
    const int tid = threadIdx.x;

    #pragma unroll
    for (int i = tid; i < LR * 32; i += 256) {
        int r = i >> 5, e = i & 31;
        As[r][e] = g_aeff[r * EDIM + e0 + e];
    }
    #pragma unroll
    for (int i = tid; i < 8 * LR; i += 256) {
        int j = i >> 7, r = i & 127;
        Bs[j][r] = B_in[(size_t)(j0 + j) * LR + r];
    }
    __syncthreads();

    const int tx = tid & 31;
    const int ty = tid >> 5;
    float acc = 0.f;
    #pragma unroll 8
    for (int r = 0; r < LR; r++)
        acc += Bs[ty][r] * As[r][tx];

    const int j = j0 + ty;
    const int e = e0 + tx;
    const float* wrow = W_in + (size_t)j * E3;
    g_wtot[(size_t)j * EDIM + e] =
        wrow[e] + wrow[e + EDIM] + wrow[e + 2 * EDIM] + LSCALE * acc;
}

// ---------------------------------------------------------------------------
// tf32 tensor-core NT GEMM: C[M,N] = A[M,K] . B[N,K]^T (both row-major).
// ---------------------------------------------------------------------------
template <int M, int N, int K>
__device__ __forceinline__ void mma_nt_body(const float* __restrict__ A,
                                            const float* __restrict__ B,
                                            float* __restrict__ C) {
    constexpr int BM = 128, BN = 128, BK = 16;
    constexpr int LD = BK + 4;
    __shared__ uint32_t As[BM * LD];
    __shared__ uint32_t Bs[BN * LD];

    const int tid  = threadIdx.x;
    const int lane = tid & 31;
    const int warp = tid >> 5;
    const int wm   = warp & 1;
    const int wn   = warp >> 1;
    const int m0   = blockIdx.y * BM;
    const int n0   = blockIdx.x * BN;

    const int srow = tid >> 2;
    const int skc  = (tid & 3) * 4;

    const float* Ab = A + (size_t)(m0 + srow) * K + skc;
    const float* Bb = B + (size_t)(n0 + srow) * K + skc;
    const size_t rstep = (size_t)64 * K;

    float4 ra0 = *(const float4*)(Ab);
    float4 ra1 = *(const float4*)(Ab + rstep);
    float4 rb0 = *(const float4*)(Bb);
    float4 rb1 = *(const float4*)(Bb + rstep);

    float acc[4][4][4];
    #pragma unroll
    for (int i = 0; i < 4; i++)
        #pragma unroll
        for (int j = 0; j < 4; j++)
            #pragma unroll
            for (int k = 0; k < 4; k++) acc[i][j][k] = 0.f;

    const int quad = lane >> 2;
    const int tq   = lane & 3;

    constexpr int T = K / BK;
    for (int t = 0; t < T; t++) {
        __syncthreads();
        {
            uint32_t* p0 = &As[srow * LD + skc];
            p0[0] = f2tf(ra0.x); p0[1] = f2tf(ra0.y); p0[2] = f2tf(ra0.z); p0[3] = f2tf(ra0.w);
            uint32_t* p1 = &As[(srow + 64) * LD + skc];
            p1[0] = f2tf(ra1.x); p1[1] = f2tf(ra1.y); p1[2] = f2tf(ra1.z); p1[3] = f2tf(ra1.w);
            uint32_t* q0 = &Bs[srow * LD + skc];
            q0[0] = f2tf(rb0.x); q0[1] = f2tf(rb0.y); q0[2] = f2tf(rb0.z); q0[3] = f2tf(rb0.w);
            uint32_t* q1 = &Bs[(srow + 64) * LD + skc];
            q1[0] = f2tf(rb1.x); q1[1] = f2tf(rb1.y); q1[2] = f2tf(rb1.z); q1[3] = f2tf(rb1.w);
        }
        __syncthreads();

        if (t + 1 < T) {
            const float* An = Ab + (t + 1) * BK;
            const float* Bn = Bb + (t + 1) * BK;
            ra0 = *(const float4*)(An);
            ra1 = *(const float4*)(An + rstep);
            rb0 = *(const float4*)(Bn);
            rb1 = *(const float4*)(Bn + rstep);
        }

        #pragma unroll
        for (int ks = 0; ks < 2; ks++) {
            const int kb = ks * 8;
            uint32_t af[4][4], bf[4][2];
            #pragma unroll
            for (int mi = 0; mi < 4; mi++) {
                const uint32_t* p = &As[(wm * 64 + mi * 16 + quad) * LD + kb + tq];
                af[mi][0] = p[0];
                af[mi][1] = p[8 * LD];
                af[mi][2] = p[4];
                af[mi][3] = p[8 * LD + 4];
            }
            #pragma unroll
            for (int ni = 0; ni < 4; ni++) {
                const uint32_t* p = &Bs[(wn * 32 + ni * 8 + quad) * LD + kb + tq];
                bf[ni][0] = p[0];
                bf[ni][1] = p[4];
            }
            #pragma unroll
            for (int mi = 0; mi < 4; mi++)
                #pragma unroll
                for (int ni = 0; ni < 4; ni++)
                    mma_tf32(acc[mi][ni], af[mi], bf[ni]);
        }
    }

    #pragma unroll
    for (int mi = 0; mi < 4; mi++) {
        const int r = m0 + wm * 64 + mi * 16 + quad;
        #pragma unroll
        for (int ni = 0; ni < 4; ni++) {
            const int c = n0 + wn * 32 + ni * 8 + tq * 2;
            *(float2*)&C[(size_t)r * N + c]       = make_float2(acc[mi][ni][0], acc[mi][ni][1]);
            *(float2*)&C[(size_t)(r + 8) * N + c] = make_float2(acc[mi][ni][2], acc[mi][ni][3]);
        }
    }
}

__global__ __launch_bounds__(256, 2) void mma_qkv_kernel(const float* __restrict__ x) {
    mma_nt_body<NTOK, E3, EDIM>(x, g_wtot, g_qkv);
}
__global__ __launch_bounds__(256, 2) void mma_out_kernel(const float* __restrict__ Wout,
                                                         float* __restrict__ out) {
    mma_nt_body<NTOK, EDIM, EDIM>(g_attn, Wout, out);
}

// ---------------------------------------------------------------------------
// Flash attention on tensor cores (tf32 m16n8k8).
// Block = 128 queries x one (b,h). 256 threads = 8 warps; warp owns 16 q rows
// and the full 64-key tile width -> softmax row stats reduce within a 4-lane
// shfl group only. K/V tiles double-buffered in dynamic smem; P staged via smem.
// LDK=68 (bank: 4q+t), LDV=72 (bank: 8t+q): all fragment LDS conflict-free.
// ---------------------------------------------------------------------------
#define AQT 128
#define AKT 64
#define LDK 68
#define LDV 72
#define LDP 68
#define KBUF (AKT * LDK)            // 4352
#define VBUF (AKT * LDV)            // 4608
#define PBUF (AQT * LDP)            // 8704
#define ASMEM_U32 (2 * KBUF + 2 * VBUF + PBUF)   // 26624
#define ASMEM_BYTES (ASMEM_U32 * 4)              // 106496

__global__ __launch_bounds__(256, 1) void attention_mma_kernel() {
    extern __shared__ uint32_t sm[];
    uint32_t* Kbuf[2] = { sm, sm + KBUF };
    uint32_t* Vbuf[2] = { sm + 2 * KBUF, sm + 2 * KBUF + VBUF };
    uint32_t* Pbuf    = sm + 2 * KBUF + 2 * VBUF;

    const int tid  = threadIdx.x;
    const int lane = tid & 31;
    const int warp = tid >> 5;
    const int quad = lane >> 2;   // 0..7  (fragment row)
    const int tq   = lane & 3;    // 0..3  (fragment k / col pair)

    const int q0 = blockIdx.x * AQT;
    const int h  = blockIdx.y;
    const int b  = blockIdx.z;

    // ---- Q fragments in registers (pre-scaled by 1/sqrt(D)=0.125) ----
    const int qrow = b * SEQ + q0 + warp * 16 + quad;
    const float* qp0 = g_qkv + (size_t)qrow * E3 + h * HD;
    const float* qp1 = qp0 + 8 * (size_t)E3;
    uint32_t qf[8][4];
    #pragma unroll
    for (int ks = 0; ks < 8; ks++) {
        qf[ks][0] = f2tf(qp0[ks * 8 + tq]     * 0.125f);
        qf[ks][1] = f2tf(qp1[ks * 8 + tq]     * 0.125f);
        qf[ks][2] = f2tf(qp0[ks * 8 + tq + 4] * 0.125f);
        qf[ks][3] = f2tf(qp1[ks * 8 + tq + 4] * 0.125f);
    }

    float oacc[8][4];
    #pragma unroll
    for (int i = 0; i < 8; i++)
        #pragma unroll
        for (int j = 0; j < 4; j++) oacc[i][j] = 0.f;
    float m0 = -1e30f, m1 = -1e30f, l0 = 0.f, l1 = 0.f;

    // K/V staging geometry: 1024 float4 per tensor tile, 4 per thread
    const float* kbase = g_qkv + ((size_t)b * SEQ) * E3 + EDIM + h * HD;
    const float* vbase = kbase + EDIM;
    const int srow = tid >> 4;          // covers rows srow, srow+16, +32, +48
    const int sc4  = (tid & 15) * 4;

    // stage tile 0
    {
        #pragma unroll
        for (int j = 0; j < 4; j++) {
            const int row = srow + j * 16;
            float4 kv = *(const float4*)(kbase + (size_t)row * E3 + sc4);
            float4 vv = *(const float4*)(vbase + (size_t)row * E3 + sc4);
            uint32_t* kp = &Kbuf[0][row * LDK + sc4];
            kp[0] = f2tf(kv.x); kp[1] = f2tf(kv.y); kp[2] = f2tf(kv.z); kp[3] = f2tf(kv.w);
            uint32_t* vp = &Vbuf[0][row * LDV + sc4];
            vp[0] = f2tf(vv.x); vp[1] = f2tf(vv.y); vp[2] = f2tf(vv.z); vp[3] = f2tf(vv.w);
        }
    }
    __syncthreads();

    uint32_t* Pw = &Pbuf[(warp * 16) * LDP];   // this warp's 16-row P slab

    constexpr int T = SEQ / AKT;   // 32
    float4 kreg[4], vreg[4];
    for (int t = 0; t < T; t++) {
        // prefetch next K/V tile into registers (hidden under compute)
        if (t + 1 < T) {
            const float* kn = kbase + (size_t)(t + 1) * AKT * E3;
            const float* vn = vbase + (size_t)(t + 1) * AKT * E3;
            #pragma unroll
            for (int j = 0; j < 4; j++) {
                const int row = srow + j * 16;
                kreg[j] = *(const float4*)(kn + (size_t)row * E3 + sc4);
                vreg[j] = *(const float4*)(vn + (size_t)row * E3 + sc4);
            }
        }

        const uint32_t* Kb = Kbuf[t & 1];
        const uint32_t* Vb = Vbuf[t & 1];

        // ---- S = Q K^T  (warp: 16 x 64) ----
        float sacc[8][4];
        #pragma unroll
        for (int i = 0; i < 8; i++)
            #pragma unroll
            for (int j = 0; j < 4; j++) sacc[i][j] = 0.f;

        #pragma unroll
        for (int ks = 0; ks < 8; ks++) {
            #pragma unroll
            for (int nf = 0; nf < 8; nf++) {
                uint32_t bf[2];
                const uint32_t* p = &Kb[(nf * 8 + quad) * LDK + ks * 8 + tq];
                bf[0] = p[0];
                bf[1] = p[4];
                mma_tf32(sacc[nf], qf[ks], bf);
            }
        }

        // ---- online softmax (rows quad, quad+8 of the warp slab) ----
        float tm0 = -1e30f, tm1 = -1e30f;
        #pragma unroll
        for (int nf = 0; nf < 8; nf++) {
            tm0 = fmaxf(tm0, fmaxf(sacc[nf][0], sacc[nf][1]));
            tm1 = fmaxf(tm1, fmaxf(sacc[nf][2], sacc[nf][3]));
        }
        tm0 = fmaxf(tm0, __shfl_xor_sync(0xffffffffu, tm0, 1));
        tm0 = fmaxf(tm0, __shfl_xor_sync(0xffffffffu, tm0, 2));
        tm1 = fmaxf(tm1, __shfl_xor_sync(0xffffffffu, tm1, 1));
        tm1 = fmaxf(tm1, __shfl_xor_sync(0xffffffffu, tm1, 2));

        const float mn0 = fmaxf(m0, tm0);
        const float mn1 = fmaxf(m1, tm1);
        const float sc0 = __expf(m0 - mn0);
        const float sc1 = __expf(m1 - mn1);

        float rs0 = 0.f, rs1 = 0.f;
        #pragma unroll
        for (int nf = 0; nf < 8; nf++) {
            const float p0 = __expf(sacc[nf][0] - mn0);
            const float p1 = __expf(sacc[nf][1] - mn0);
            const float p2 = __expf(sacc[nf][2] - mn1);
            const float p3 = __expf(sacc[nf][3] - mn1);
            rs0 += p0 + p1;
            rs1 += p2 + p3;
            uint32_t* pr0 = &Pw[quad * LDP + nf * 8 + tq * 2];
            pr0[0] = f2tf(p0); pr0[1] = f2tf(p1);
            uint32_t* pr1 = &Pw[(quad + 8) * LDP + nf * 8 + tq * 2];
            pr1[0] = f2tf(p2); pr1[1] = f2tf(p3);
        }
        rs0 += __shfl_xor_sync(0xffffffffu, rs0, 1);
        rs0 += __shfl_xor_sync(0xffffffffu, rs0, 2);
        rs1 += __shfl_xor_sync(0xffffffffu, rs1, 1);
        rs1 += __shfl_xor_sync(0xffffffffu, rs1, 2);

        l0 = l0 * sc0 + rs0;
        l1 = l1 * sc1 + rs1;
        m0 = mn0;
        m1 = mn1;
        #pragma unroll
        for (int onf = 0; onf < 8; onf++) {
            oacc[onf][0] *= sc0; oacc[onf][1] *= sc0;
            oacc[onf][2] *= sc1; oacc[onf][3] *= sc1;
        }
        __syncwarp();

        // ---- O += P V  (warp: 16 x 64, k = 64 keys) ----
        #pragma unroll
        for (int ks = 0; ks < 8; ks++) {
            uint32_t af[4];
            const uint32_t* pa0 = &Pw[quad * LDP + ks * 8 + tq];
            const uint32_t* pa1 = &Pw[(quad + 8) * LDP + ks * 8 + tq];
            af[0] = pa0[0];
            af[1] = pa1[0];
            af[2] = pa0[4];
            af[3] = pa1[4];
            #pragma unroll
            for (int onf = 0; onf < 8; onf++) {
                uint32_t bf[2];
                bf[0] = Vb[(ks * 8 + tq) * LDV + onf * 8 + quad];
                bf[1] = Vb[(ks * 8 + tq + 4) * LDV + onf * 8 + quad];
                mma_tf32(oacc[onf], af, bf);
            }
        }

        __syncthreads();   // all warps done reading buf[(t+1)&1] (last read iter t-1)
        if (t + 1 < T) {
            uint32_t* Kn = Kbuf[(t + 1) & 1];
            uint32_t* Vn = Vbuf[(t + 1) & 1];
            #pragma unroll
            for (int j = 0; j < 4; j++) {
                const int row = srow + j * 16;
                uint32_t* kp = &Kn[row * LDK + sc4];
                kp[0] = f2tf(kreg[j].x); kp[1] = f2tf(kreg[j].y);
                kp[2] = f2tf(kreg[j].z); kp[3] = f2tf(kreg[j].w);
                uint32_t* vp = &Vn[row * LDV + sc4];
                vp[0] = f2tf(vreg[j].x); vp[1] = f2tf(vreg[j].y);
                vp[2] = f2tf(vreg[j].z); vp[3] = f2tf(vreg[j].w);
            }
        }
        __syncthreads();   // staged tile visible for next iter
    }

    // ---- epilogue ----
    const float inv0 = 1.f / l0;
    const float inv1 = 1.f / l1;
    const int row0 = b * SEQ + q0 + warp * 16 + quad;
    const int row1 = row0 + 8;
    #pragma unroll
    for (int onf = 0; onf < 8; onf++) {
        const int col = h * HD + onf * 8 + tq * 2;
        *(float2*)&g_attn[(size_t)row0 * EDIM + col] =
            make_float2(oacc[onf][0] * inv0, oacc[onf][1] * inv0);
        *(float2*)&g_attn[(size_t)row1 * EDIM + col] =
            make_float2(oacc[onf][2] * inv1, oacc[onf][3] * inv1);
    }
}

// ---------------------------------------------------------------------------
// Launch
// ---------------------------------------------------------------------------
extern "C" void kernel_launch(void* const* d_in, const int* in_sizes, int n_in,
                              void* d_out, int out_size) {
    const float* x     = (const float*)d_in[0];
    const float* W_in  = (const float*)d_in[1];
    const float* A_in  = (const float*)d_in[2];
    const float* B_in  = (const float*)d_in[3];
    const float* W_out = (const float*)d_in[4];
    float* out = (float*)d_out;

    cudaFuncSetAttribute(attention_mma_kernel,
                         cudaFuncAttributeMaxDynamicSharedMemorySize, ASMEM_BYTES);

    aeff_kernel<<<(LR * EDIM + 255) / 256, 256>>>(A_in);
    wtotal_kernel<<<dim3(EDIM / 32, E3 / 8), 256>>>(W_in, B_in);
    mma_qkv_kernel<<<dim3(E3 / 128, NTOK / 128), 256>>>(x);
    attention_mma_kernel<<<dim3(SEQ / AQT, NH, NB), 256, ASMEM_BYTES>>>();
    mma_out_kernel<<<dim3(EDIM / 128, NTOK / 128), 256>>>(W_out, out);
}

// round 5
// speedup vs baseline: 4.6680x; 1.1115x over previous
#include <cuda_runtime.h>
#include <cstdint>

// Problem constants
#define EDIM   1024
#define NH     16
#define HD     64
#define SEQ    2048
#define NB     2
#define NTOK   (NB * SEQ)      // 4096 tokens
#define E3     (3 * EDIM)      // 3072
#define LR     128             // LoRA rank
#define LSCALE (1.0f / 128.0f) // lora scaling

// Scratch (no cudaMalloc allowed -> __device__ globals)
__device__ float g_aeff[LR * EDIM];
__device__ float g_wtot[E3 * EDIM];
__device__ float g_qkv[(size_t)NTOK * E3];
__device__ float g_attn[(size_t)NTOK * EDIM];

// ---------------------------------------------------------------------------
// helpers
// ---------------------------------------------------------------------------
__device__ __forceinline__ uint32_t f2tf(float f) {
    uint32_t u;
    asm("cvt.rna.tf32.f32 %0, %1;" : "=r"(u) : "f"(f));
    return u;
}
__device__ __forceinline__ float ex2f(float x) {
    float y;
    asm("ex2.approx.ftz.f32 %0, %1;" : "=f"(y) : "f"(x));
    return y;
}
__device__ __forceinline__ void mma_tf32(float* d, const uint32_t* a, const uint32_t* b) {
    asm volatile(
        "mma.sync.aligned.m16n8k8.row.col.f32.tf32.tf32.f32 "
        "{%0,%1,%2,%3}, {%4,%5,%6,%7}, {%8,%9}, {%0,%1,%2,%3};\n"
        : "+f"(d[0]), "+f"(d[1]), "+f"(d[2]), "+f"(d[3])
        : "r"(a[0]), "r"(a[1]), "r"(a[2]), "r"(a[3]), "r"(b[0]), "r"(b[1]));
}

// ---------------------------------------------------------------------------
// Kernel 1: A_eff[r,e] = A_in[r,e] + A_in[r,E+e] + A_in[r,2E+e]
// ---------------------------------------------------------------------------
__global__ void aeff_kernel(const float* __restrict__ A_in) {
    int i = blockIdx.x * blockDim.x + threadIdx.x;
    if (i >= LR * EDIM) return;
    int r = i >> 10;
    int e = i & (EDIM - 1);
    const float* row = A_in + (size_t)r * E3;
    g_aeff[i] = row[e] + row[e + EDIM] + row[e + 2 * EDIM];
}

// ---------------------------------------------------------------------------
// Kernel 2: W_total[j,e] = W_eff + s * B_in @ A_eff
// ---------------------------------------------------------------------------
__global__ __launch_bounds__(256) void wtotal_kernel(const float* __restrict__ W_in,
                                                     const float* __restrict__ B_in) {
    __shared__ float As[LR][32];
    __shared__ float Bs[8][LR];
    const int e0 = blockIdx.x * 32;
    const int j0 = blockIdx.y * 8;
    const int tid = threadIdx.x;

    #pragma unroll
    for (int i = tid; i < LR * 32; i += 256) {
        int r = i >> 5, e = i & 31;
        As[r][e] = g_aeff[r * EDIM + e0 + e];
    }
    #pragma unroll
    for (int i = tid; i < 8 * LR; i += 256) {
        int j = i >> 7, r = i & 127;
        Bs[j][r] = B_in[(size_t)(j0 + j) * LR + r];
    }
    __syncthreads();

    const int tx = tid & 31;
    const int ty = tid >> 5;
    float acc = 0.f;
    #pragma unroll 8
    for (int r = 0; r < LR; r++)
        acc += Bs[ty][r] * As[r][tx];

    const int j = j0 + ty;
    const int e = e0 + tx;
    const float* wrow = W_in + (size_t)j * E3;
    g_wtot[(size_t)j * EDIM + e] =
        wrow[e] + wrow[e + EDIM] + wrow[e + 2 * EDIM] + LSCALE * acc;
}

// ---------------------------------------------------------------------------
// tf32 tensor-core NT GEMM: C[M,N] = A[M,K] . B[N,K]^T (both row-major).
// ---------------------------------------------------------------------------
template <int M, int N, int K>
__device__ __forceinline__ void mma_nt_body(const float* __restrict__ A,
                                            const float* __restrict__ B,
                                            float* __restrict__ C) {
    constexpr int BM = 128, BN = 128, BK = 16;
    constexpr int LD = BK + 4;
    __shared__ uint32_t As[BM * LD];
    __shared__ uint32_t Bs[BN * LD];

    const int tid  = threadIdx.x;
    const int lane = tid & 31;
    const int warp = tid >> 5;
    const int wm   = warp & 1;
    const int wn   = warp >> 1;
    const int m0   = blockIdx.y * BM;
    const int n0   = blockIdx.x * BN;

    const int srow = tid >> 2;
    const int skc  = (tid & 3) * 4;

    const float* Ab = A + (size_t)(m0 + srow) * K + skc;
    const float* Bb = B + (size_t)(n0 + srow) * K + skc;
    const size_t rstep = (size_t)64 * K;

    float4 ra0 = *(const float4*)(Ab);
    float4 ra1 = *(const float4*)(Ab + rstep);
    float4 rb0 = *(const float4*)(Bb);
    float4 rb1 = *(const float4*)(Bb + rstep);

    float acc[4][4][4];
    #pragma unroll
    for (int i = 0; i < 4; i++)
        #pragma unroll
        for (int j = 0; j < 4; j++)
            #pragma unroll
            for (int k = 0; k < 4; k++) acc[i][j][k] = 0.f;

    const int quad = lane >> 2;
    const int tq   = lane & 3;

    constexpr int T = K / BK;
    for (int t = 0; t < T; t++) {
        __syncthreads();
        {
            uint32_t* p0 = &As[srow * LD + skc];
            p0[0] = f2tf(ra0.x); p0[1] = f2tf(ra0.y); p0[2] = f2tf(ra0.z); p0[3] = f2tf(ra0.w);
            uint32_t* p1 = &As[(srow + 64) * LD + skc];
            p1[0] = f2tf(ra1.x); p1[1] = f2tf(ra1.y); p1[2] = f2tf(ra1.z); p1[3] = f2tf(ra1.w);
            uint32_t* q0 = &Bs[srow * LD + skc];
            q0[0] = f2tf(rb0.x); q0[1] = f2tf(rb0.y); q0[2] = f2tf(rb0.z); q0[3] = f2tf(rb0.w);
            uint32_t* q1 = &Bs[(srow + 64) * LD + skc];
            q1[0] = f2tf(rb1.x); q1[1] = f2tf(rb1.y); q1[2] = f2tf(rb1.z); q1[3] = f2tf(rb1.w);
        }
        __syncthreads();

        if (t + 1 < T) {
            const float* An = Ab + (t + 1) * BK;
            const float* Bn = Bb + (t + 1) * BK;
            ra0 = *(const float4*)(An);
            ra1 = *(const float4*)(An + rstep);
            rb0 = *(const float4*)(Bn);
            rb1 = *(const float4*)(Bn + rstep);
        }

        #pragma unroll
        for (int ks = 0; ks < 2; ks++) {
            const int kb = ks * 8;
            uint32_t af[4][4], bf[4][2];
            #pragma unroll
            for (int mi = 0; mi < 4; mi++) {
                const uint32_t* p = &As[(wm * 64 + mi * 16 + quad) * LD + kb + tq];
                af[mi][0] = p[0];
                af[mi][1] = p[8 * LD];
                af[mi][2] = p[4];
                af[mi][3] = p[8 * LD + 4];
            }
            #pragma unroll
            for (int ni = 0; ni < 4; ni++) {
                const uint32_t* p = &Bs[(wn * 32 + ni * 8 + quad) * LD + kb + tq];
                bf[ni][0] = p[0];
                bf[ni][1] = p[4];
            }
            #pragma unroll
            for (int mi = 0; mi < 4; mi++)
                #pragma unroll
                for (int ni = 0; ni < 4; ni++)
                    mma_tf32(acc[mi][ni], af[mi], bf[ni]);
        }
    }

    #pragma unroll
    for (int mi = 0; mi < 4; mi++) {
        const int r = m0 + wm * 64 + mi * 16 + quad;
        #pragma unroll
        for (int ni = 0; ni < 4; ni++) {
            const int c = n0 + wn * 32 + ni * 8 + tq * 2;
            *(float2*)&C[(size_t)r * N + c]       = make_float2(acc[mi][ni][0], acc[mi][ni][1]);
            *(float2*)&C[(size_t)(r + 8) * N + c] = make_float2(acc[mi][ni][2], acc[mi][ni][3]);
        }
    }
}

__global__ __launch_bounds__(256, 2) void mma_qkv_kernel(const float* __restrict__ x) {
    mma_nt_body<NTOK, E3, EDIM>(x, g_wtot, g_qkv);
}
__global__ __launch_bounds__(256, 2) void mma_out_kernel(const float* __restrict__ Wout,
                                                         float* __restrict__ out) {
    mma_nt_body<NTOK, EDIM, EDIM>(g_attn, Wout, out);
}

// ---------------------------------------------------------------------------
// Flash attention, tf32 mma, 2 CTAs/SM.
// Block = 128 q x one (b,h); 8 warps x (16q x 32k tile per iter, T=64 iters).
// Fragment-paired smem layouts:
//   K: [nf:4][ks:8(stride 66)][quad:8][tq:4][2]   -> QK B-frag = 1 LDS.64
//   V: [onf:8][ks:4][quad:8][tq:4][2]             -> PV B-frag = 1 LDS.64
//   P: [warp][ks:4][quad:8][16]                   -> PV A-frag = 1 LDS.128
// Softmax in log2 domain (log2e folded into Q scale, raw ex2.approx).
// One __syncthreads per iter (double-buffered K/V, write target last read
// two iters ago behind the previous barrier).
// ---------------------------------------------------------------------------
#define AQT 128
#define AKT 32
#define KSTRIDE 66
#define KBUFN (4 * 8 * KSTRIDE)          // 2112 u32
#define VBUFN (8 * 4 * 64)               // 2048 u32
#define POFF  (2 * KBUFN + 2 * VBUFN)    // 8320
#define ASMEM_U32 (POFF + 8 * 512)       // 12416
#define ASMEM_BYTES (ASMEM_U32 * 4)      // 49664

__global__ __launch_bounds__(256, 2) void attention_mma_kernel() {
    extern __shared__ uint32_t sm[];

    const int tid  = threadIdx.x;
    const int lane = tid & 31;
    const int warp = tid >> 5;
    const int quad = lane >> 2;
    const int tq   = lane & 3;

    const int q0 = blockIdx.x * AQT;
    const int h  = blockIdx.y;
    const int b  = blockIdx.z;

    // ---- Q fragments (scale = 1/sqrt(64) * log2(e)) ----
    const float QS = 0.125f * 1.4426950408889634f;
    const int qrow = b * SEQ + q0 + warp * 16 + quad;
    const float* qp0 = g_qkv + (size_t)qrow * E3 + h * HD;
    const float* qp1 = qp0 + 8 * (size_t)E3;
    uint32_t qf[8][4];
    #pragma unroll
    for (int ks = 0; ks < 8; ks++) {
        qf[ks][0] = f2tf(qp0[ks * 8 + tq]     * QS);
        qf[ks][1] = f2tf(qp1[ks * 8 + tq]     * QS);
        qf[ks][2] = f2tf(qp0[ks * 8 + tq + 4] * QS);
        qf[ks][3] = f2tf(qp1[ks * 8 + tq + 4] * QS);
    }

    float oacc[8][4];
    #pragma unroll
    for (int i = 0; i < 8; i++)
        #pragma unroll
        for (int j = 0; j < 4; j++) oacc[i][j] = 0.f;
    float m0 = -1e30f, m1 = -1e30f, l0 = 0.f, l1 = 0.f;

    // ---- staging geometry: 2 float4 per tensor per thread ----
    const int r0 = tid >> 4;            // rows r0, r0+16 of the 32-key tile
    const int c4 = (tid & 15) * 4;      // d offset
    const float* kbase = g_qkv + ((size_t)b * SEQ) * E3 + EDIM + h * HD;
    const float* vbase = kbase + EDIM;

    // smem write offsets (u32), per j in {0,1}: row = r0 + 16*j
    int koff[2], voff[2];
    #pragma unroll
    for (int j = 0; j < 2; j++) {
        const int r = r0 + 16 * j;
        koff[j] = (r >> 3) * (8 * KSTRIDE) + (c4 >> 3) * KSTRIDE + (r & 7) * 8 + ((c4 >> 2) & 1);
        voff[j] = (c4 >> 3) * 256 + (r >> 3) * 64 + (c4 & 7) * 8 + (r & 3) * 2 + ((r >> 2) & 1);
    }

    // stage tile 0 into buffer 0
    #pragma unroll
    for (int j = 0; j < 2; j++) {
        const int r = r0 + 16 * j;
        float4 kv = *(const float4*)(kbase + (size_t)r * E3 + c4);
        float4 vv = *(const float4*)(vbase + (size_t)r * E3 + c4);
        uint32_t* kp = sm + koff[j];
        kp[0] = f2tf(kv.x); kp[2] = f2tf(kv.y); kp[4] = f2tf(kv.z); kp[6] = f2tf(kv.w);
        uint32_t* vp = sm + 2 * KBUFN + voff[j];
        vp[0] = f2tf(vv.x); vp[8] = f2tf(vv.y); vp[16] = f2tf(vv.z); vp[24] = f2tf(vv.w);
    }
    __syncthreads();

    uint32_t* Pw = sm + POFF + warp * 512;
    const int sA = ((2 * tq) & 3) * 4 + (tq >> 1) * 2;      // (p0,p2) slot
    const int sB = ((2 * tq + 1) & 3) * 4 + (tq >> 1) * 2;  // (p1,p3) slot

    constexpr int T = SEQ / AKT;   // 64
    float4 kreg[2], vreg[2];
    for (int t = 0; t < T; t++) {
        // prefetch next tile to registers
        if (t + 1 < T) {
            const float* kn = kbase + (size_t)(t + 1) * AKT * E3;
            const float* vn = vbase + (size_t)(t + 1) * AKT * E3;
            #pragma unroll
            for (int j = 0; j < 2; j++) {
                const int r = r0 + 16 * j;
                kreg[j] = *(const float4*)(kn + (size_t)r * E3 + c4);
                vreg[j] = *(const float4*)(vn + (size_t)r * E3 + c4);
            }
        }

        const uint32_t* Kc = sm + (t & 1) * KBUFN;
        const uint32_t* Vc = sm + 2 * KBUFN + (t & 1) * VBUFN;

        // ---- S = Q K^T (16 x 32 per warp) ----
        float sacc[4][4];
        #pragma unroll
        for (int i = 0; i < 4; i++)
            #pragma unroll
            for (int j = 0; j < 4; j++) sacc[i][j] = 0.f;

        #pragma unroll
        for (int ks = 0; ks < 8; ks++) {
            #pragma unroll
            for (int nf = 0; nf < 4; nf++) {
                uint2 bp = *(const uint2*)&Kc[nf * (8 * KSTRIDE) + ks * KSTRIDE + quad * 8 + tq * 2];
                uint32_t bf[2] = { bp.x, bp.y };
                mma_tf32(sacc[nf], qf[ks], bf);
            }
        }

        // ---- online softmax (log2 domain) ----
        float tm0 = -1e30f, tm1 = -1e30f;
        #pragma unroll
        for (int nf = 0; nf < 4; nf++) {
            tm0 = fmaxf(tm0, fmaxf(sacc[nf][0], sacc[nf][1]));
            tm1 = fmaxf(tm1, fmaxf(sacc[nf][2], sacc[nf][3]));
        }
        tm0 = fmaxf(tm0, __shfl_xor_sync(0xffffffffu, tm0, 1));
        tm0 = fmaxf(tm0, __shfl_xor_sync(0xffffffffu, tm0, 2));
        tm1 = fmaxf(tm1, __shfl_xor_sync(0xffffffffu, tm1, 1));
        tm1 = fmaxf(tm1, __shfl_xor_sync(0xffffffffu, tm1, 2));

        const float mn0 = fmaxf(m0, tm0);
        const float mn1 = fmaxf(m1, tm1);
        const float sc0 = ex2f(m0 - mn0);
        const float sc1 = ex2f(m1 - mn1);

        float rs0 = 0.f, rs1 = 0.f;
        #pragma unroll
        for (int nf = 0; nf < 4; nf++) {
            const float p0 = ex2f(sacc[nf][0] - mn0);
            const float p1 = ex2f(sacc[nf][1] - mn0);
            const float p2 = ex2f(sacc[nf][2] - mn1);
            const float p3 = ex2f(sacc[nf][3] - mn1);
            rs0 += p0 + p1;
            rs1 += p2 + p3;
            uint32_t* pb = Pw + nf * 128 + quad * 16;
            *(uint2*)&pb[sA] = make_uint2(f2tf(p0), f2tf(p2));
            *(uint2*)&pb[sB] = make_uint2(f2tf(p1), f2tf(p3));
        }
        rs0 += __shfl_xor_sync(0xffffffffu, rs0, 1);
        rs0 += __shfl_xor_sync(0xffffffffu, rs0, 2);
        rs1 += __shfl_xor_sync(0xffffffffu, rs1, 1);
        rs1 += __shfl_xor_sync(0xffffffffu, rs1, 2);

        l0 = l0 * sc0 + rs0;
        l1 = l1 * sc1 + rs1;
        m0 = mn0;
        m1 = mn1;
        #pragma unroll
        for (int onf = 0; onf < 8; onf++) {
            oacc[onf][0] *= sc0; oacc[onf][1] *= sc0;
            oacc[onf][2] *= sc1; oacc[onf][3] *= sc1;
        }
        __syncwarp();

        // ---- O += P V (16 x 64, k = 32 keys) ----
        #pragma unroll
        for (int ks = 0; ks < 4; ks++) {
            uint4 ap = *(const uint4*)&Pw[ks * 128 + quad * 16 + tq * 4];
            uint32_t af[4] = { ap.x, ap.y, ap.z, ap.w };
            #pragma unroll
            for (int onf = 0; onf < 8; onf++) {
                uint2 bp = *(const uint2*)&Vc[onf * 256 + ks * 64 + quad * 8 + tq * 2];
                uint32_t bf[2] = { bp.x, bp.y };
                mma_tf32(oacc[onf], af, bf);
            }
        }

        // ---- stage prefetched tile into the other buffer ----
        if (t + 1 < T) {
            uint32_t* Kn = sm + ((t + 1) & 1) * KBUFN;
            uint32_t* Vn = sm + 2 * KBUFN + ((t + 1) & 1) * VBUFN;
            #pragma unroll
            for (int j = 0; j < 2; j++) {
                uint32_t* kp = Kn + koff[j];
                kp[0] = f2tf(kreg[j].x); kp[2] = f2tf(kreg[j].y);
                kp[4] = f2tf(kreg[j].z); kp[6] = f2tf(kreg[j].w);
                uint32_t* vp = Vn + voff[j];
                vp[0] = f2tf(vreg[j].x); vp[8] = f2tf(vreg[j].y);
                vp[16] = f2tf(vreg[j].z); vp[24] = f2tf(vreg[j].w);
            }
        }
        __syncthreads();
    }

    // ---- epilogue ----
    const float inv0 = 1.f / l0;
    const float inv1 = 1.f / l1;
    const int row0 = b * SEQ + q0 + warp * 16 + quad;
    const int row1 = row0 + 8;
    #pragma unroll
    for (int onf = 0; onf < 8; onf++) {
        const int col = h * HD + onf * 8 + tq * 2;
        *(float2*)&g_attn[(size_t)row0 * EDIM + col] =
            make_float2(oacc[onf][0] * inv0, oacc[onf][1] * inv0);
        *(float2*)&g_attn[(size_t)row1 * EDIM + col] =
            make_float2(oacc[onf][2] * inv1, oacc[onf][3] * inv1);
    }
}

// ---------------------------------------------------------------------------
// Launch
// ---------------------------------------------------------------------------
extern "C" void kernel_launch(void* const* d_in, const int* in_sizes, int n_in,
                              void* d_out, int out_size) {
    const float* x     = (const float*)d_in[0];
    const float* W_in  = (const float*)d_in[1];
    const float* A_in  = (const float*)d_in[2];
    const float* B_in  = (const float*)d_in[3];
    const float* W_out = (const float*)d_in[4];
    float* out = (float*)d_out;

    cudaFuncSetAttribute(attention_mma_kernel,
                         cudaFuncAttributeMaxDynamicSharedMemorySize, ASMEM_BYTES);

    aeff_kernel<<<(LR * EDIM + 255) / 256, 256>>>(A_in);
    wtotal_kernel<<<dim3(EDIM / 32, E3 / 8), 256>>>(W_in, B_in);
    mma_qkv_kernel<<<dim3(E3 / 128, NTOK / 128), 256>>>(x);
    attention_mma_kernel<<<dim3(SEQ / AQT, NH, NB), 256, ASMEM_BYTES>>>();
    mma_out_kernel<<<dim3(EDIM / 128, NTOK / 128), 256>>>(W_out, out);
}

// round 7
// speedup vs baseline: 6.4063x; 1.3724x over previous
#include <cuda_runtime.h>
#include <cstdint>

// Problem constants
#define EDIM   1024
#define NH     16
#define HD     64
#define SEQ    2048
#define NB     2
#define NTOK   (NB * SEQ)      // 4096 tokens
#define E3     (3 * EDIM)      // 3072
#define LR     128             // LoRA rank
#define LSCALE (1.0f / 128.0f) // lora scaling

// Scratch (no cudaMalloc allowed -> __device__ globals)
__device__ float g_aeff[LR * EDIM];
__device__ float g_wtot[E3 * EDIM];
__device__ float g_qkv[(size_t)NTOK * E3];
__device__ float g_attn[(size_t)NTOK * EDIM];

// ---------------------------------------------------------------------------
// helpers
// ---------------------------------------------------------------------------
__device__ __forceinline__ uint32_t f2tf(float f) {
    uint32_t u;
    asm("cvt.rna.tf32.f32 %0, %1;" : "=r"(u) : "f"(f));
    return u;
}
__device__ __forceinline__ float ex2f(float x) {
    float y;
    asm("ex2.approx.ftz.f32 %0, %1;" : "=f"(y) : "f"(x));
    return y;
}
// pack two floats into f16x2: lo -> bits[15:0], hi -> bits[31:16]
__device__ __forceinline__ uint32_t packhf(float lo, float hi) {
    uint32_t d;
    asm("cvt.rn.f16x2.f32 %0, %1, %2;" : "=r"(d) : "f"(hi), "f"(lo));
    return d;
}
__device__ __forceinline__ void mma_tf32(float* d, const uint32_t* a, const uint32_t* b) {
    asm volatile(
        "mma.sync.aligned.m16n8k8.row.col.f32.tf32.tf32.f32 "
        "{%0,%1,%2,%3}, {%4,%5,%6,%7}, {%8,%9}, {%0,%1,%2,%3};\n"
        : "+f"(d[0]), "+f"(d[1]), "+f"(d[2]), "+f"(d[3])
        : "r"(a[0]), "r"(a[1]), "r"(a[2]), "r"(a[3]), "r"(b[0]), "r"(b[1]));
}
__device__ __forceinline__ void mma_f16(float* d, const uint32_t* a, uint32_t b0, uint32_t b1) {
    asm volatile(
        "mma.sync.aligned.m16n8k16.row.col.f32.f16.f16.f32 "
        "{%0,%1,%2,%3}, {%4,%5,%6,%7}, {%8,%9}, {%0,%1,%2,%3};\n"
        : "+f"(d[0]), "+f"(d[1]), "+f"(d[2]), "+f"(d[3])
        : "r"(a[0]), "r"(a[1]), "r"(a[2]), "r"(a[3]), "r"(b0), "r"(b1));
}

// ---------------------------------------------------------------------------
// Kernel 1: A_eff[r,e] = A_in[r,e] + A_in[r,E+e] + A_in[r,2E+e]
// ---------------------------------------------------------------------------
__global__ void aeff_kernel(const float* __restrict__ A_in) {
    int i = blockIdx.x * blockDim.x + threadIdx.x;
    if (i >= LR * EDIM) return;
    int r = i >> 10;
    int e = i & (EDIM - 1);
    const float* row = A_in + (size_t)r * E3;
    g_aeff[i] = row[e] + row[e + EDIM] + row[e + 2 * EDIM];
}

// ---------------------------------------------------------------------------
// Kernel 2: W_total[j,e] = W_eff + s * B_in @ A_eff
// ---------------------------------------------------------------------------
__global__ __launch_bounds__(256) void wtotal_kernel(const float* __restrict__ W_in,
                                                     const float* __restrict__ B_in) {
    __shared__ float As[LR][32];
    __shared__ float Bs[8][LR];
    const int e0 = blockIdx.x * 32;
    const int j0 = blockIdx.y * 8;
    const int tid = threadIdx.x;

    #pragma unroll
    for (int i = tid; i < LR * 32; i += 256) {
        int r = i >> 5, e = i & 31;
        As[r][e] = g_aeff[r * EDIM + e0 + e];
    }
    #pragma unroll
    for (int i = tid; i < 8 * LR; i += 256) {
        int j = i >> 7, r = i & 127;
        Bs[j][r] = B_in[(size_t)(j0 + j) * LR + r];
    }
    __syncthreads();

    const int tx = tid & 31;
    const int ty = tid >> 5;
    float acc = 0.f;
    #pragma unroll 8
    for (int r = 0; r < LR; r++)
        acc += Bs[ty][r] * As[r][tx];

    const int j = j0 + ty;
    const int e = e0 + tx;
    const float* wrow = W_in + (size_t)j * E3;
    g_wtot[(size_t)j * EDIM + e] =
        wrow[e] + wrow[e + EDIM] + wrow[e + 2 * EDIM] + LSCALE * acc;
}

// ---------------------------------------------------------------------------
// tf32 tensor-core NT GEMM: C[M,N] = A[M,K] . B[N,K]^T (both row-major).
// Double-buffered smem: ONE barrier per k-tile.
// ---------------------------------------------------------------------------
template <int M, int N, int K>
__device__ __forceinline__ void mma_nt_body(const float* __restrict__ A,
                                            const float* __restrict__ B,
                                            float* __restrict__ C) {
    constexpr int BM = 128, BN = 128, BK = 16;
    constexpr int LD = BK + 4;
    __shared__ uint32_t As[2][BM * LD];
    __shared__ uint32_t Bs[2][BM * LD];

    const int tid  = threadIdx.x;
    const int lane = tid & 31;
    const int warp = tid >> 5;
    const int wm   = warp & 1;
    const int wn   = warp >> 1;
    const int m0   = blockIdx.y * BM;
    const int n0   = blockIdx.x * BN;

    const int srow = tid >> 2;
    const int skc  = (tid & 3) * 4;

    const float* Ab = A + (size_t)(m0 + srow) * K + skc;
    const float* Bb = B + (size_t)(n0 + srow) * K + skc;
    const size_t rstep = (size_t)64 * K;

    float acc[4][4][4];
    #pragma unroll
    for (int i = 0; i < 4; i++)
        #pragma unroll
        for (int j = 0; j < 4; j++)
            #pragma unroll
            for (int k = 0; k < 4; k++) acc[i][j][k] = 0.f;

    const int quad = lane >> 2;
    const int tq   = lane & 3;

    // stage tile 0 into buffer 0
    {
        float4 ra0 = *(const float4*)(Ab);
        float4 ra1 = *(const float4*)(Ab + rstep);
        float4 rb0 = *(const float4*)(Bb);
        float4 rb1 = *(const float4*)(Bb + rstep);
        uint32_t* p0 = &As[0][srow * LD + skc];
        p0[0] = f2tf(ra0.x); p0[1] = f2tf(ra0.y); p0[2] = f2tf(ra0.z); p0[3] = f2tf(ra0.w);
        uint32_t* p1 = &As[0][(srow + 64) * LD + skc];
        p1[0] = f2tf(ra1.x); p1[1] = f2tf(ra1.y); p1[2] = f2tf(ra1.z); p1[3] = f2tf(ra1.w);
        uint32_t* q0 = &Bs[0][srow * LD + skc];
        q0[0] = f2tf(rb0.x); q0[1] = f2tf(rb0.y); q0[2] = f2tf(rb0.z); q0[3] = f2tf(rb0.w);
        uint32_t* q1 = &Bs[0][(srow + 64) * LD + skc];
        q1[0] = f2tf(rb1.x); q1[1] = f2tf(rb1.y); q1[2] = f2tf(rb1.z); q1[3] = f2tf(rb1.w);
    }
    __syncthreads();

    constexpr int T = K / BK;
    float4 ra0, ra1, rb0, rb1;
    for (int t = 0; t < T; t++) {
        if (t + 1 < T) {
            const float* An = Ab + (t + 1) * BK;
            const float* Bn = Bb + (t + 1) * BK;
            ra0 = *(const float4*)(An);
            ra1 = *(const float4*)(An + rstep);
            rb0 = *(const float4*)(Bn);
            rb1 = *(const float4*)(Bn + rstep);
        }

        const uint32_t* Ac = As[t & 1];
        const uint32_t* Bc = Bs[t & 1];
        #pragma unroll
        for (int ks = 0; ks < 2; ks++) {
            const int kb = ks * 8;
            uint32_t af[4][4], bf[4][2];
            #pragma unroll
            for (int mi = 0; mi < 4; mi++) {
                const uint32_t* p = &Ac[(wm * 64 + mi * 16 + quad) * LD + kb + tq];
                af[mi][0] = p[0];
                af[mi][1] = p[8 * LD];
                af[mi][2] = p[4];
                af[mi][3] = p[8 * LD + 4];
            }
            #pragma unroll
            for (int ni = 0; ni < 4; ni++) {
                const uint32_t* p = &Bc[(wn * 32 + ni * 8 + quad) * LD + kb + tq];
                bf[ni][0] = p[0];
                bf[ni][1] = p[4];
            }
            #pragma unroll
            for (int mi = 0; mi < 4; mi++)
                #pragma unroll
                for (int ni = 0; ni < 4; ni++)
                    mma_tf32(acc[mi][ni], af[mi], bf[ni]);
        }

        if (t + 1 < T) {
            uint32_t* p0 = &As[(t + 1) & 1][srow * LD + skc];
            p0[0] = f2tf(ra0.x); p0[1] = f2tf(ra0.y); p0[2] = f2tf(ra0.z); p0[3] = f2tf(ra0.w);
            uint32_t* p1 = &As[(t + 1) & 1][(srow + 64) * LD + skc];
            p1[0] = f2tf(ra1.x); p1[1] = f2tf(ra1.y); p1[2] = f2tf(ra1.z); p1[3] = f2tf(ra1.w);
            uint32_t* q0 = &Bs[(t + 1) & 1][srow * LD + skc];
            q0[0] = f2tf(rb0.x); q0[1] = f2tf(rb0.y); q0[2] = f2tf(rb0.z); q0[3] = f2tf(rb0.w);
            uint32_t* q1 = &Bs[(t + 1) & 1][(srow + 64) * LD + skc];
            q1[0] = f2tf(rb1.x); q1[1] = f2tf(rb1.y); q1[2] = f2tf(rb1.z); q1[3] = f2tf(rb1.w);
        }
        __syncthreads();
    }

    #pragma unroll
    for (int mi = 0; mi < 4; mi++) {
        const int r = m0 + wm * 64 + mi * 16 + quad;
        #pragma unroll
        for (int ni = 0; ni < 4; ni++) {
            const int c = n0 + wn * 32 + ni * 8 + tq * 2;
            *(float2*)&C[(size_t)r * N + c]       = make_float2(acc[mi][ni][0], acc[mi][ni][1]);
            *(float2*)&C[(size_t)(r + 8) * N + c] = make_float2(acc[mi][ni][2], acc[mi][ni][3]);
        }
    }
}

__global__ __launch_bounds__(256, 2) void mma_qkv_kernel(const float* __restrict__ x) {
    mma_nt_body<NTOK, E3, EDIM>(x, g_wtot, g_qkv);
}
__global__ __launch_bounds__(256, 2) void mma_out_kernel(const float* __restrict__ Wout,
                                                         float* __restrict__ out) {
    mma_nt_body<NTOK, EDIM, EDIM>(g_attn, Wout, out);
}

// ---------------------------------------------------------------------------
// Flash attention: QK in tf32 (m16n8k8), PV in fp16 (m16n8k16).
// P never touches smem: the QK C-fragment layout IS the PV 16-bit A-fragment
// layout after pairwise packing (FA2 register-direct path). fp16 (10-bit
// mantissa) instead of bf16 keeps the quantization error ~8x lower; P in
// (0,1] and V = O(5) are far inside fp16 range.
// K smem:  [nf:4][ks:8 (stride 66)][quad:8][tq-pairs]  -> B-frag = LDS.64
// V smem (f16x2 words, pair = 2 consecutive keys):
//          [onf:8 (stride 132)][g:2][quad:8][slot(p)]  -> B-frag = LDS.64
// One __syncthreads per iter; double-buffered K/V; reg-staged prefetch.
// ---------------------------------------------------------------------------
#define AQT 128
#define AKT 32
#define KSTRIDE 66
#define KBUFN (4 * 8 * KSTRIDE)          // 2112 u32
#define VBUFN 1056                       // 8 * 132 u32 (f16x2 words)
#define ASMEM_U32 (2 * KBUFN + 2 * VBUFN)  // 6336
#define ASMEM_BYTES (ASMEM_U32 * 4)        // 25344

__global__ __launch_bounds__(256, 2) void attention_mma_kernel() {
    extern __shared__ uint32_t sm[];

    const int tid  = threadIdx.x;
    const int lane = tid & 31;
    const int warp = tid >> 5;
    const int quad = lane >> 2;
    const int tq   = lane & 3;

    const int q0 = blockIdx.x * AQT;
    const int h  = blockIdx.y;
    const int b  = blockIdx.z;

    // ---- Q fragments (scale = 1/sqrt(64) * log2(e)) ----
    const float QS = 0.125f * 1.4426950408889634f;
    const int qrow = b * SEQ + q0 + warp * 16 + quad;
    const float* qp0 = g_qkv + (size_t)qrow * E3 + h * HD;
    const float* qp1 = qp0 + 8 * (size_t)E3;
    uint32_t qf[8][4];
    #pragma unroll
    for (int ks = 0; ks < 8; ks++) {
        qf[ks][0] = f2tf(qp0[ks * 8 + tq]     * QS);
        qf[ks][1] = f2tf(qp1[ks * 8 + tq]     * QS);
        qf[ks][2] = f2tf(qp0[ks * 8 + tq + 4] * QS);
        qf[ks][3] = f2tf(qp1[ks * 8 + tq + 4] * QS);
    }

    float oacc[8][4];
    #pragma unroll
    for (int i = 0; i < 8; i++)
        #pragma unroll
        for (int j = 0; j < 4; j++) oacc[i][j] = 0.f;
    float m0 = -1e30f, m1 = -1e30f, l0 = 0.f, l1 = 0.f;

    // ---- staging geometry ----
    const int r0 = tid >> 4;            // K rows r0, r0+16
    const int av = tid >> 4;            // V key-pair index 0..15 (keys 2av, 2av+1)
    const int c4 = (tid & 15) * 4;      // dim offset
    const float* kbase = g_qkv + ((size_t)b * SEQ) * E3 + EDIM + h * HD;
    const float* vbase = kbase + EDIM;

    // K smem write offsets (u32), j in {0,1}: row = r0 + 16*j, 4 dims stride 2
    int koff[2];
    #pragma unroll
    for (int j = 0; j < 2; j++) {
        const int r = r0 + 16 * j;
        koff[j] = (r >> 3) * (8 * KSTRIDE) + (c4 >> 3) * KSTRIDE + (r & 7) * 8 + ((c4 >> 2) & 1);
    }
    // V smem write base (f16x2 words): dims c4..c4+3 at stride 8
    const int vslot = (av & 3) * 2 + ((av >> 2) & 1);
    const int voffb = (c4 >> 3) * 132 + (av >> 3) * 64 + (c4 & 7) * 8 + vslot;

    // stage tile 0 into buffer 0
    {
        #pragma unroll
        for (int j = 0; j < 2; j++) {
            const int r = r0 + 16 * j;
            float4 kv = *(const float4*)(kbase + (size_t)r * E3 + c4);
            uint32_t* kp = sm + koff[j];
            kp[0] = f2tf(kv.x); kp[2] = f2tf(kv.y); kp[4] = f2tf(kv.z); kp[6] = f2tf(kv.w);
        }
        float4 v0 = *(const float4*)(vbase + (size_t)(2 * av) * E3 + c4);
        float4 v1 = *(const float4*)(vbase + (size_t)(2 * av + 1) * E3 + c4);
        uint32_t* vp = sm + 2 * KBUFN + voffb;
        vp[0]  = packhf(v0.x, v1.x);
        vp[8]  = packhf(v0.y, v1.y);
        vp[16] = packhf(v0.z, v1.z);
        vp[24] = packhf(v0.w, v1.w);
    }
    __syncthreads();

    constexpr int T = SEQ / AKT;   // 64
    float4 kreg[2], vreg0, vreg1;
    for (int t = 0; t < T; t++) {
        // prefetch next tile to registers
        if (t + 1 < T) {
            const float* kn = kbase + (size_t)(t + 1) * AKT * E3;
            const float* vn = vbase + (size_t)(t + 1) * AKT * E3;
            #pragma unroll
            for (int j = 0; j < 2; j++)
                kreg[j] = *(const float4*)(kn + (size_t)(r0 + 16 * j) * E3 + c4);
            vreg0 = *(const float4*)(vn + (size_t)(2 * av) * E3 + c4);
            vreg1 = *(const float4*)(vn + (size_t)(2 * av + 1) * E3 + c4);
        }

        const uint32_t* Kc = sm + (t & 1) * KBUFN;
        const uint32_t* Vc = sm + 2 * KBUFN + (t & 1) * VBUFN;

        // ---- S = Q K^T (16 x 32 per warp, tf32) ----
        float sacc[4][4];
        #pragma unroll
        for (int i = 0; i < 4; i++)
            #pragma unroll
            for (int j = 0; j < 4; j++) sacc[i][j] = 0.f;

        #pragma unroll
        for (int ks = 0; ks < 8; ks++) {
            #pragma unroll
            for (int nf = 0; nf < 4; nf++) {
                uint2 bp = *(const uint2*)&Kc[nf * (8 * KSTRIDE) + ks * KSTRIDE + quad * 8 + tq * 2];
                uint32_t bf[2] = { bp.x, bp.y };
                mma_tf32(sacc[nf], qf[ks], bf);
            }
        }

        // ---- online softmax (log2 domain), exps written back into sacc ----
        float tm0 = -1e30f, tm1 = -1e30f;
        #pragma unroll
        for (int nf = 0; nf < 4; nf++) {
            tm0 = fmaxf(tm0, fmaxf(sacc[nf][0], sacc[nf][1]));
            tm1 = fmaxf(tm1, fmaxf(sacc[nf][2], sacc[nf][3]));
        }
        tm0 = fmaxf(tm0, __shfl_xor_sync(0xffffffffu, tm0, 1));
        tm0 = fmaxf(tm0, __shfl_xor_sync(0xffffffffu, tm0, 2));
        tm1 = fmaxf(tm1, __shfl_xor_sync(0xffffffffu, tm1, 1));
        tm1 = fmaxf(tm1, __shfl_xor_sync(0xffffffffu, tm1, 2));

        const float mn0 = fmaxf(m0, tm0);
        const float mn1 = fmaxf(m1, tm1);
        const float sc0 = ex2f(m0 - mn0);
        const float sc1 = ex2f(m1 - mn1);

        float rs0 = 0.f, rs1 = 0.f;
        #pragma unroll
        for (int nf = 0; nf < 4; nf++) {
            sacc[nf][0] = ex2f(sacc[nf][0] - mn0);
            sacc[nf][1] = ex2f(sacc[nf][1] - mn0);
            sacc[nf][2] = ex2f(sacc[nf][2] - mn1);
            sacc[nf][3] = ex2f(sacc[nf][3] - mn1);
            rs0 += sacc[nf][0] + sacc[nf][1];
            rs1 += sacc[nf][2] + sacc[nf][3];
        }
        rs0 += __shfl_xor_sync(0xffffffffu, rs0, 1);
        rs0 += __shfl_xor_sync(0xffffffffu, rs0, 2);
        rs1 += __shfl_xor_sync(0xffffffffu, rs1, 1);
        rs1 += __shfl_xor_sync(0xffffffffu, rs1, 2);

        l0 = l0 * sc0 + rs0;
        l1 = l1 * sc1 + rs1;
        m0 = mn0;
        m1 = mn1;
        #pragma unroll
        for (int onf = 0; onf < 8; onf++) {
            oacc[onf][0] *= sc0; oacc[onf][1] *= sc0;
            oacc[onf][2] *= sc1; oacc[onf][3] *= sc1;
        }

        // ---- O += P V (fp16 m16n8k16): P direct from registers ----
        #pragma unroll
        for (int g2 = 0; g2 < 2; g2++) {
            uint32_t af[4];
            af[0] = packhf(sacc[2 * g2][0],     sacc[2 * g2][1]);
            af[1] = packhf(sacc[2 * g2][2],     sacc[2 * g2][3]);
            af[2] = packhf(sacc[2 * g2 + 1][0], sacc[2 * g2 + 1][1]);
            af[3] = packhf(sacc[2 * g2 + 1][2], sacc[2 * g2 + 1][3]);
            #pragma unroll
            for (int onf = 0; onf < 8; onf++) {
                uint2 bp = *(const uint2*)&Vc[onf * 132 + g2 * 64 + quad * 8 + tq * 2];
                mma_f16(oacc[onf], af, bp.x, bp.y);
            }
        }

        // ---- stage prefetched tile into the other buffer ----
        if (t + 1 < T) {
            uint32_t* Kn = sm + ((t + 1) & 1) * KBUFN;
            uint32_t* Vn = sm + 2 * KBUFN + ((t + 1) & 1) * VBUFN;
            #pragma unroll
            for (int j = 0; j < 2; j++) {
                uint32_t* kp = Kn + koff[j];
                kp[0] = f2tf(kreg[j].x); kp[2] = f2tf(kreg[j].y);
                kp[4] = f2tf(kreg[j].z); kp[6] = f2tf(kreg[j].w);
            }
            uint32_t* vp = Vn + voffb;
            vp[0]  = packhf(vreg0.x, vreg1.x);
            vp[8]  = packhf(vreg0.y, vreg1.y);
            vp[16] = packhf(vreg0.z, vreg1.z);
            vp[24] = packhf(vreg0.w, vreg1.w);
        }
        __syncthreads();
    }

    // ---- epilogue ----
    const float inv0 = 1.f / l0;
    const float inv1 = 1.f / l1;
    const int row0 = b * SEQ + q0 + warp * 16 + quad;
    const int row1 = row0 + 8;
    #pragma unroll
    for (int onf = 0; onf < 8; onf++) {
        const int col = h * HD + onf * 8 + tq * 2;
        *(float2*)&g_attn[(size_t)row0 * EDIM + col] =
            make_float2(oacc[onf][0] * inv0, oacc[onf][1] * inv0);
        *(float2*)&g_attn[(size_t)row1 * EDIM + col] =
            make_float2(oacc[onf][2] * inv1, oacc[onf][3] * inv1);
    }
}

// ---------------------------------------------------------------------------
// Launch
// ---------------------------------------------------------------------------
extern "C" void kernel_launch(void* const* d_in, const int* in_sizes, int n_in,
                              void* d_out, int out_size) {
    const float* x     = (const float*)d_in[0];
    const float* W_in  = (const float*)d_in[1];
    const float* A_in  = (const float*)d_in[2];
    const float* B_in  = (const float*)d_in[3];
    const float* W_out = (const float*)d_in[4];
    float* out = (float*)d_out;

    cudaFuncSetAttribute(attention_mma_kernel,
                         cudaFuncAttributeMaxDynamicSharedMemorySize, ASMEM_BYTES);

    aeff_kernel<<<(LR * EDIM + 255) / 256, 256>>>(A_in);
    wtotal_kernel<<<dim3(EDIM / 32, E3 / 8), 256>>>(W_in, B_in);
    mma_qkv_kernel<<<dim3(E3 / 128, NTOK / 128), 256>>>(x);
    attention_mma_kernel<<<dim3(SEQ / AQT, NH, NB), 256, ASMEM_BYTES>>>();
    mma_out_kernel<<<dim3(EDIM / 128, NTOK / 128), 256>>>(W_out, out);
}

// round 8
// speedup vs baseline: 6.5356x; 1.0202x over previous
#include <cuda_runtime.h>
#include <cstdint>

// Problem constants
#define EDIM   1024
#define NH     16
#define HD     64
#define SEQ    2048
#define NB     2
#define NTOK   (NB * SEQ)      // 4096 tokens
#define E3     (3 * EDIM)      // 3072
#define LR     128             // LoRA rank
#define LSCALE (1.0f / 128.0f) // lora scaling

#define AQT 128
#define AKT 32
#define NT  (SEQ / AKT)        // 64 key tiles per (b,h)
#define KTILE_U32 2112         // K tile: [nf:4][ks:8 stride66][quad:8][pairs]
#define VTILE_U32 1056         // V tile: [onf:8 stride132][g2:2][quad:8][slots] f16x2
#define TILE_U32  (KTILE_U32 + VTILE_U32)   // 3168 u32 = 12672 B (16B multiple)
#define TILE_CHUNKS (TILE_U32 / 4)          // 792 x 16B

// Scratch (no cudaMalloc allowed -> __device__ globals)
__device__ float g_aeff[LR * EDIM];
__device__ float g_wtot[E3 * EDIM];
__device__ float g_qkv[(size_t)NTOK * E3];
__device__ float g_attn[(size_t)NTOK * EDIM];
__device__ __align__(16) uint32_t g_kv[(size_t)NB * NH * NT * TILE_U32];  // ~26 MB

// ---------------------------------------------------------------------------
// helpers
// ---------------------------------------------------------------------------
__device__ __forceinline__ uint32_t f2tf(float f) {
    uint32_t u;
    asm("cvt.rna.tf32.f32 %0, %1;" : "=r"(u) : "f"(f));
    return u;
}
__device__ __forceinline__ float ex2f(float x) {
    float y;
    asm("ex2.approx.ftz.f32 %0, %1;" : "=f"(y) : "f"(x));
    return y;
}
__device__ __forceinline__ uint32_t packhf(float lo, float hi) {
    uint32_t d;
    asm("cvt.rn.f16x2.f32 %0, %1, %2;" : "=r"(d) : "f"(hi), "f"(lo));
    return d;
}
__device__ __forceinline__ void mma_tf32(float* d, const uint32_t* a, const uint32_t* b) {
    asm volatile(
        "mma.sync.aligned.m16n8k8.row.col.f32.tf32.tf32.f32 "
        "{%0,%1,%2,%3}, {%4,%5,%6,%7}, {%8,%9}, {%0,%1,%2,%3};\n"
        : "+f"(d[0]), "+f"(d[1]), "+f"(d[2]), "+f"(d[3])
        : "r"(a[0]), "r"(a[1]), "r"(a[2]), "r"(a[3]), "r"(b[0]), "r"(b[1]));
}
__device__ __forceinline__ void mma_f16(float* d, const uint32_t* a, uint32_t b0, uint32_t b1) {
    asm volatile(
        "mma.sync.aligned.m16n8k16.row.col.f32.f16.f16.f32 "
        "{%0,%1,%2,%3}, {%4,%5,%6,%7}, {%8,%9}, {%0,%1,%2,%3};\n"
        : "+f"(d[0]), "+f"(d[1]), "+f"(d[2]), "+f"(d[3])
        : "r"(a[0]), "r"(a[1]), "r"(a[2]), "r"(a[3]), "r"(b0), "r"(b1));
}
__device__ __forceinline__ void cp_async16(uint32_t smem_addr, const void* gptr) {
    asm volatile("cp.async.cg.shared.global [%0], [%1], 16;" :: "r"(smem_addr), "l"(gptr));
}

// ---------------------------------------------------------------------------
// Kernel 1: A_eff[r,e] = A_in[r,e] + A_in[r,E+e] + A_in[r,2E+e]
// ---------------------------------------------------------------------------
__global__ void aeff_kernel(const float* __restrict__ A_in) {
    int i = blockIdx.x * blockDim.x + threadIdx.x;
    if (i >= LR * EDIM) return;
    int r = i >> 10;
    int e = i & (EDIM - 1);
    const float* row = A_in + (size_t)r * E3;
    g_aeff[i] = row[e] + row[e + EDIM] + row[e + 2 * EDIM];
}

// ---------------------------------------------------------------------------
// Kernel 2: W_total[j,e] = W_eff + s * B_in @ A_eff
// ---------------------------------------------------------------------------
__global__ __launch_bounds__(256) void wtotal_kernel(const float* __restrict__ W_in,
                                                     const float* __restrict__ B_in) {
    __shared__ float As[LR][32];
    __shared__ float Bs[8][LR];
    const int e0 = blockIdx.x * 32;
    const int j0 = blockIdx.y * 8;
    const int tid = threadIdx.x;

    #pragma unroll
    for (int i = tid; i < LR * 32; i += 256) {
        int r = i >> 5, e = i & 31;
        As[r][e] = g_aeff[r * EDIM + e0 + e];
    }
    #pragma unroll
    for (int i = tid; i < 8 * LR; i += 256) {
        int j = i >> 7, r = i & 127;
        Bs[j][r] = B_in[(size_t)(j0 + j) * LR + r];
    }
    __syncthreads();

    const int tx = tid & 31;
    const int ty = tid >> 5;
    float acc = 0.f;
    #pragma unroll 8
    for (int r = 0; r < LR; r++)
        acc += Bs[ty][r] * As[r][tx];

    const int j = j0 + ty;
    const int e = e0 + tx;
    const float* wrow = W_in + (size_t)j * E3;
    g_wtot[(size_t)j * EDIM + e] =
        wrow[e] + wrow[e + EDIM] + wrow[e + 2 * EDIM] + LSCALE * acc;
}

// ---------------------------------------------------------------------------
// tf32 tensor-core NT GEMM: C[M,N] = A[M,K] . B[N,K]^T (both row-major).
// Fragment-paired smem layouts: each A fragment = 2 LDS.64, B = 1 LDS.64
// (pairs (k, k+4) stored adjacent). Double-buffered, one barrier per k-tile.
//   A: off(row,k) = (row>>4)*260 + (k>>3)*130 + (row&15)*8 + (k&3)*2 + ((k>>2)&1)
//   B: off(n,k)   = (n>>3)*132  + (k>>3)*66  + (n&7)*8    + (k&3)*2 + ((k>>2)&1)
// Fragment reads at quad*8 + tq*2 -> bijection onto even banks per half-warp.
// ---------------------------------------------------------------------------
template <int M, int N, int K>
__device__ __forceinline__ void mma_nt_body(const float* __restrict__ A,
                                            const float* __restrict__ B,
                                            float* __restrict__ C) {
    constexpr int BM = 128, BN = 128, BK = 16;
    __shared__ uint32_t As[2][8 * 260];    // 2080 u32 per buffer
    __shared__ uint32_t Bs[2][16 * 132];   // 2112 u32 per buffer

    const int tid  = threadIdx.x;
    const int lane = tid & 31;
    const int warp = tid >> 5;
    const int wm   = warp & 1;
    const int wn   = warp >> 1;
    const int m0   = blockIdx.y * BM;
    const int n0   = blockIdx.x * BN;

    const int srow = tid >> 2;            // 0..63
    const int skc  = (tid & 3) * 4;       // k offset 0,4,8,12
    const int ksS  = skc >> 3;
    const int hfS  = (skc >> 2) & 1;

    // store bases (loop-invariant)
    const int aoff0 = (srow >> 4) * 260 + ksS * 130 + (srow & 15) * 8 + hfS;
    const int aoff1 = aoff0 + 4 * 260;                       // row + 64
    const int boff0 = (srow >> 3) * 132 + ksS * 66 + (srow & 7) * 8 + hfS;
    const int boff1 = boff0 + 8 * 132;                       // row + 64

    const float* Ab = A + (size_t)(m0 + srow) * K + skc;
    const float* Bb = B + (size_t)(n0 + srow) * K + skc;
    const size_t rstep = (size_t)64 * K;

    float acc[4][4][4];
    #pragma unroll
    for (int i = 0; i < 4; i++)
        #pragma unroll
        for (int j = 0; j < 4; j++)
            #pragma unroll
            for (int k = 0; k < 4; k++) acc[i][j][k] = 0.f;

    const int quad = lane >> 2;
    const int tq   = lane & 3;

    // stage tile 0 into buffer 0
    {
        float4 ra0 = *(const float4*)(Ab);
        float4 ra1 = *(const float4*)(Ab + rstep);
        float4 rb0 = *(const float4*)(Bb);
        float4 rb1 = *(const float4*)(Bb + rstep);
        uint32_t* a0 = &As[0][aoff0];
        a0[0] = f2tf(ra0.x); a0[2] = f2tf(ra0.y); a0[4] = f2tf(ra0.z); a0[6] = f2tf(ra0.w);
        uint32_t* a1 = &As[0][aoff1];
        a1[0] = f2tf(ra1.x); a1[2] = f2tf(ra1.y); a1[4] = f2tf(ra1.z); a1[6] = f2tf(ra1.w);
        uint32_t* b0 = &Bs[0][boff0];
        b0[0] = f2tf(rb0.x); b0[2] = f2tf(rb0.y); b0[4] = f2tf(rb0.z); b0[6] = f2tf(rb0.w);
        uint32_t* b1 = &Bs[0][boff1];
        b1[0] = f2tf(rb1.x); b1[2] = f2tf(rb1.y); b1[4] = f2tf(rb1.z); b1[6] = f2tf(rb1.w);
    }
    __syncthreads();

    constexpr int T = K / BK;
    float4 ra0, ra1, rb0, rb1;
    for (int t = 0; t < T; t++) {
        if (t + 1 < T) {
            const float* An = Ab + (t + 1) * BK;
            const float* Bn = Bb + (t + 1) * BK;
            ra0 = *(const float4*)(An);
            ra1 = *(const float4*)(An + rstep);
            rb0 = *(const float4*)(Bn);
            rb1 = *(const float4*)(Bn + rstep);
        }

        const uint32_t* Ac = As[t & 1];
        const uint32_t* Bc = Bs[t & 1];
        #pragma unroll
        for (int ks = 0; ks < 2; ks++) {
            uint32_t af[4][4], bf[4][2];
            #pragma unroll
            for (int mi = 0; mi < 4; mi++) {
                const uint32_t* pa = &Ac[(wm * 4 + mi) * 260 + ks * 130 + quad * 8 + tq * 2];
                uint2 a01 = *(const uint2*)pa;          // (row,   k) , (row,   k+4)
                uint2 a23 = *(const uint2*)(pa + 64);   // (row+8, k) , (row+8, k+4)
                af[mi][0] = a01.x; af[mi][1] = a23.x;
                af[mi][2] = a01.y; af[mi][3] = a23.y;
            }
            #pragma unroll
            for (int ni = 0; ni < 4; ni++) {
                uint2 b01 = *(const uint2*)&Bc[(wn * 4 + ni) * 132 + ks * 66 + quad * 8 + tq * 2];
                bf[ni][0] = b01.x; bf[ni][1] = b01.y;
            }
            #pragma unroll
            for (int mi = 0; mi < 4; mi++)
                #pragma unroll
                for (int ni = 0; ni < 4; ni++)
                    mma_tf32(acc[mi][ni], af[mi], bf[ni]);
        }

        if (t + 1 < T) {
            uint32_t* a0 = &As[(t + 1) & 1][aoff0];
            a0[0] = f2tf(ra0.x); a0[2] = f2tf(ra0.y); a0[4] = f2tf(ra0.z); a0[6] = f2tf(ra0.w);
            uint32_t* a1 = &As[(t + 1) & 1][aoff1];
            a1[0] = f2tf(ra1.x); a1[2] = f2tf(ra1.y); a1[4] = f2tf(ra1.z); a1[6] = f2tf(ra1.w);
            uint32_t* b0 = &Bs[(t + 1) & 1][boff0];
            b0[0] = f2tf(rb0.x); b0[2] = f2tf(rb0.y); b0[4] = f2tf(rb0.z); b0[6] = f2tf(rb0.w);
            uint32_t* b1 = &Bs[(t + 1) & 1][boff1];
            b1[0] = f2tf(rb1.x); b1[2] = f2tf(rb1.y); b1[4] = f2tf(rb1.z); b1[6] = f2tf(rb1.w);
        }
        __syncthreads();
    }

    #pragma unroll
    for (int mi = 0; mi < 4; mi++) {
        const int r = m0 + wm * 64 + mi * 16 + quad;
        #pragma unroll
        for (int ni = 0; ni < 4; ni++) {
            const int c = n0 + wn * 32 + ni * 8 + tq * 2;
            *(float2*)&C[(size_t)r * N + c]       = make_float2(acc[mi][ni][0], acc[mi][ni][1]);
            *(float2*)&C[(size_t)(r + 8) * N + c] = make_float2(acc[mi][ni][2], acc[mi][ni][3]);
        }
    }
}

__global__ __launch_bounds__(256, 2) void mma_qkv_kernel(const float* __restrict__ x) {
    mma_nt_body<NTOK, E3, EDIM>(x, g_wtot, g_qkv);
}
__global__ __launch_bounds__(256, 2) void mma_out_kernel(const float* __restrict__ Wout,
                                                         float* __restrict__ out) {
    mma_nt_body<NTOK, EDIM, EDIM>(g_attn, Wout, out);
}

// ---------------------------------------------------------------------------
// kvconv: pre-convert K (tf32) and V (f16x2 key-pairs) into gmem tiles laid
// out EXACTLY as the attention kernel's smem fragment layout, so the attention
// hot loop can cp.async them in with zero conversion / zero STS work.
// One block per (t, h, b) tile; 256 threads (same mapping as old staging).
// ---------------------------------------------------------------------------
__global__ __launch_bounds__(256) void kvconv_kernel() {
    const int t = blockIdx.x, h = blockIdx.y, b = blockIdx.z;
    const int tid = threadIdx.x;
    const int r0 = tid >> 4;
    const int av = tid >> 4;
    const int c4 = (tid & 15) * 4;

    const float* kbase = g_qkv + ((size_t)b * SEQ + (size_t)t * AKT) * E3 + EDIM + h * HD;
    const float* vbase = kbase + EDIM;
    uint32_t* dst = g_kv + ((size_t)(b * NH + h) * NT + t) * TILE_U32;

    #pragma unroll
    for (int j = 0; j < 2; j++) {
        const int r = r0 + 16 * j;
        float4 kv = *(const float4*)(kbase + (size_t)r * E3 + c4);
        const int ko = (r >> 3) * (8 * 66) + (c4 >> 3) * 66 + (r & 7) * 8 + ((c4 >> 2) & 1);
        dst[ko]     = f2tf(kv.x);
        dst[ko + 2] = f2tf(kv.y);
        dst[ko + 4] = f2tf(kv.z);
        dst[ko + 6] = f2tf(kv.w);
    }
    float4 v0 = *(const float4*)(vbase + (size_t)(2 * av) * E3 + c4);
    float4 v1 = *(const float4*)(vbase + (size_t)(2 * av + 1) * E3 + c4);
    const int vslot = (av & 3) * 2 + ((av >> 2) & 1);
    const int vo = KTILE_U32 + (c4 >> 3) * 132 + (av >> 3) * 64 + (c4 & 7) * 8 + vslot;
    dst[vo]      = packhf(v0.x, v1.x);
    dst[vo + 8]  = packhf(v0.y, v1.y);
    dst[vo + 16] = packhf(v0.z, v1.z);
    dst[vo + 24] = packhf(v0.w, v1.w);
}

// ---------------------------------------------------------------------------
// Flash attention: QK tf32, PV fp16, P register-direct (FA2).
// K/V tiles arrive pre-converted + pre-laid-out via cp.async, 4-stage ring.
// One __syncthreads per iter; dummy commit_groups keep wait_group counting
// uniform through the tail.
// ---------------------------------------------------------------------------
#define STAGES 4
#define ASMEM_BYTES (STAGES * TILE_U32 * 4)   // 50688

__device__ __forceinline__ void kv_issue(uint32_t smem_dst_addr, const uint32_t* src, int tid) {
    #pragma unroll
    for (int j = 0; j < 4; j++) {
        const int idx = tid + j * 256;
        if (idx < TILE_CHUNKS)
            cp_async16(smem_dst_addr + idx * 16, src + idx * 4);
    }
    asm volatile("cp.async.commit_group;");
}

__global__ __launch_bounds__(256, 2) void attention_mma_kernel() {
    extern __shared__ uint32_t sm[];

    const int tid  = threadIdx.x;
    const int lane = tid & 31;
    const int warp = tid >> 5;
    const int quad = lane >> 2;
    const int tq   = lane & 3;

    const int q0 = blockIdx.x * AQT;
    const int h  = blockIdx.y;
    const int b  = blockIdx.z;

    const uint32_t* kvbase = g_kv + (size_t)(b * NH + h) * NT * TILE_U32;
    const uint32_t smbase = (uint32_t)__cvta_generic_to_shared(sm);

    // kick off first STAGES-1 tiles
    #pragma unroll
    for (int s = 0; s < STAGES - 1; s++)
        kv_issue(smbase + s * (TILE_U32 * 4), kvbase + (size_t)s * TILE_U32, tid);

    // ---- Q fragments (scale = 1/sqrt(64) * log2(e)) ----
    const float QS = 0.125f * 1.4426950408889634f;
    const int qrow = b * SEQ + q0 + warp * 16 + quad;
    const float* qp0 = g_qkv + (size_t)qrow * E3 + h * HD;
    const float* qp1 = qp0 + 8 * (size_t)E3;
    uint32_t qf[8][4];
    #pragma unroll
    for (int ks = 0; ks < 8; ks++) {
        qf[ks][0] = f2tf(qp0[ks * 8 + tq]     * QS);
        qf[ks][1] = f2tf(qp1[ks * 8 + tq]     * QS);
        qf[ks][2] = f2tf(qp0[ks * 8 + tq + 4] * QS);
        qf[ks][3] = f2tf(qp1[ks * 8 + tq + 4] * QS);
    }

    float oacc[8][4];
    #pragma unroll
    for (int i = 0; i < 8; i++)
        #pragma unroll
        for (int j = 0; j < 4; j++) oacc[i][j] = 0.f;
    float m0 = -1e30f, m1 = -1e30f, l0 = 0.f, l1 = 0.f;

    for (int t = 0; t < NT; t++) {
        asm volatile("cp.async.wait_group 2;");
        __syncthreads();

        // keep the group counter moving even in the tail
        if (t + STAGES - 1 < NT)
            kv_issue(smbase + ((t + STAGES - 1) & (STAGES - 1)) * (TILE_U32 * 4),
                     kvbase + (size_t)(t + STAGES - 1) * TILE_U32, tid);
        else
            asm volatile("cp.async.commit_group;");

        const uint32_t* Kc = sm + (t & (STAGES - 1)) * TILE_U32;
        const uint32_t* Vc = Kc + KTILE_U32;

        // ---- S = Q K^T (16 x 32 per warp, tf32) ----
        float sacc[4][4];
        #pragma unroll
        for (int i = 0; i < 4; i++)
            #pragma unroll
            for (int j = 0; j < 4; j++) sacc[i][j] = 0.f;

        #pragma unroll
        for (int ks = 0; ks < 8; ks++) {
            #pragma unroll
            for (int nf = 0; nf < 4; nf++) {
                uint2 bp = *(const uint2*)&Kc[nf * (8 * 66) + ks * 66 + quad * 8 + tq * 2];
                uint32_t bf[2] = { bp.x, bp.y };
                mma_tf32(sacc[nf], qf[ks], bf);
            }
        }

        // ---- online softmax (log2 domain), exps written back into sacc ----
        float tm0 = -1e30f, tm1 = -1e30f;
        #pragma unroll
        for (int nf = 0; nf < 4; nf++) {
            tm0 = fmaxf(tm0, fmaxf(sacc[nf][0], sacc[nf][1]));
            tm1 = fmaxf(tm1, fmaxf(sacc[nf][2], sacc[nf][3]));
        }
        tm0 = fmaxf(tm0, __shfl_xor_sync(0xffffffffu, tm0, 1));
        tm0 = fmaxf(tm0, __shfl_xor_sync(0xffffffffu, tm0, 2));
        tm1 = fmaxf(tm1, __shfl_xor_sync(0xffffffffu, tm1, 1));
        tm1 = fmaxf(tm1, __shfl_xor_sync(0xffffffffu, tm1, 2));

        const float mn0 = fmaxf(m0, tm0);
        const float mn1 = fmaxf(m1, tm1);
        const float sc0 = ex2f(m0 - mn0);
        const float sc1 = ex2f(m1 - mn1);

        float rs0 = 0.f, rs1 = 0.f;
        #pragma unroll
        for (int nf = 0; nf < 4; nf++) {
            sacc[nf][0] = ex2f(sacc[nf][0] - mn0);
            sacc[nf][1] = ex2f(sacc[nf][1] - mn0);
            sacc[nf][2] = ex2f(sacc[nf][2] - mn1);
            sacc[nf][3] = ex2f(sacc[nf][3] - mn1);
            rs0 += sacc[nf][0] + sacc[nf][1];
            rs1 += sacc[nf][2] + sacc[nf][3];
        }
        rs0 += __shfl_xor_sync(0xffffffffu, rs0, 1);
        rs0 += __shfl_xor_sync(0xffffffffu, rs0, 2);
        rs1 += __shfl_xor_sync(0xffffffffu, rs1, 1);
        rs1 += __shfl_xor_sync(0xffffffffu, rs1, 2);

        l0 = l0 * sc0 + rs0;
        l1 = l1 * sc1 + rs1;
        m0 = mn0;
        m1 = mn1;
        #pragma unroll
        for (int onf = 0; onf < 8; onf++) {
            oacc[onf][0] *= sc0; oacc[onf][1] *= sc0;
            oacc[onf][2] *= sc1; oacc[onf][3] *= sc1;
        }

        // ---- O += P V (fp16 m16n8k16): P direct from registers ----
        #pragma unroll
        for (int g2 = 0; g2 < 2; g2++) {
            uint32_t af[4];
            af[0] = packhf(sacc[2 * g2][0],     sacc[2 * g2][1]);
            af[1] = packhf(sacc[2 * g2][2],     sacc[2 * g2][3]);
            af[2] = packhf(sacc[2 * g2 + 1][0], sacc[2 * g2 + 1][1]);
            af[3] = packhf(sacc[2 * g2 + 1][2], sacc[2 * g2 + 1][3]);
            #pragma unroll
            for (int onf = 0; onf < 8; onf++) {
                uint2 bp = *(const uint2*)&Vc[onf * 132 + g2 * 64 + quad * 8 + tq * 2];
                mma_f16(oacc[onf], af, bp.x, bp.y);
            }
        }
    }

    // ---- epilogue ----
    const float inv0 = 1.f / l0;
    const float inv1 = 1.f / l1;
    const int row0 = b * SEQ + q0 + warp * 16 + quad;
    const int row1 = row0 + 8;
    #pragma unroll
    for (int onf = 0; onf < 8; onf++) {
        const int col = h * HD + onf * 8 + tq * 2;
        *(float2*)&g_attn[(size_t)row0 * EDIM + col] =
            make_float2(oacc[onf][0] * inv0, oacc[onf][1] * inv0);
        *(float2*)&g_attn[(size_t)row1 * EDIM + col] =
            make_float2(oacc[onf][2] * inv1, oacc[onf][3] * inv1);
    }
}

// ---------------------------------------------------------------------------
// Launch
// ---------------------------------------------------------------------------
extern "C" void kernel_launch(void* const* d_in, const int* in_sizes, int n_in,
                              void* d_out, int out_size) {
    const float* x     = (const float*)d_in[0];
    const float* W_in  = (const float*)d_in[1];
    const float* A_in  = (const float*)d_in[2];
    const float* B_in  = (const float*)d_in[3];
    const float* W_out = (const float*)d_in[4];
    float* out = (float*)d_out;

    cudaFuncSetAttribute(attention_mma_kernel,
                         cudaFuncAttributeMaxDynamicSharedMemorySize, ASMEM_BYTES);

    aeff_kernel<<<(LR * EDIM + 255) / 256, 256>>>(A_in);
    wtotal_kernel<<<dim3(EDIM / 32, E3 / 8), 256>>>(W_in, B_in);
    mma_qkv_kernel<<<dim3(E3 / 128, NTOK / 128), 256>>>(x);
    kvconv_kernel<<<dim3(NT, NH, NB), 256>>>();
    attention_mma_kernel<<<dim3(SEQ / AQT, NH, NB), 256, ASMEM_BYTES>>>();
    mma_out_kernel<<<dim3(EDIM / 128, NTOK / 128), 256>>>(W_out, out);
}